// round 1
// baseline (speedup 1.0000x reference)
#include <cuda_runtime.h>
#include <math.h>

// Problem constants (fixed shapes)
#define NB   2
#define CH   256
#define INC  128
#define ITC  16
#define NPT  32
#define HL   64
#define WL   64
#define NPIX 4096      // HL*WL
#define HH   32
#define WH   32

// ---------------- scratch (static __device__, no allocs) ----------------
__device__ float g_high_up[NB * CH  * NPIX];   // [B,256,4096]
__device__ float g_qf     [NB * INC * NPIX];   // [B,128,4096]
__device__ float g_vf     [NB * INC * NPIX];   // [B,128,4096]
__device__ float g_q      [NB * ITC * NPIX];   // [B,16,4096]
__device__ float g_off    [NB * 2*NPT * NPIX]; // [B,64,4096]
__device__ float g_kcm    [NB * ITC * NPIX];   // k channel-major
__device__ float g_vcm    [NB * INC * NPIX];   // v channel-major
__device__ float g_kT     [NB * NPIX * ITC];   // k NHWC
__device__ float g_vT     [NB * NPIX * INC];   // v NHWC
__device__ float g_attn   [NB * INC * NPIX];   // attention output, channel-major

// ---------------- bilinear 2x upsample (half-pixel, border clamp) -------
__global__ void upsample_kernel(const float* __restrict__ hi, float* __restrict__ out) {
    int idx = blockIdx.x * blockDim.x + threadIdx.x;
    if (idx >= NB * CH * NPIX) return;
    int pos = idx & (NPIX - 1);
    int bc  = idx >> 12;
    int y = pos >> 6, x = pos & 63;
    float fx = x * 0.5f - 0.25f;
    float fy = y * 0.5f - 0.25f;
    float x0f = floorf(fx), y0f = floorf(fy);
    float wx = fx - x0f,    wy = fy - y0f;
    int ix0 = min(max((int)x0f, 0), WH - 1);
    int ix1 = min(max((int)x0f + 1, 0), WH - 1);
    int iy0 = min(max((int)y0f, 0), HH - 1);
    int iy1 = min(max((int)y0f + 1, 0), HH - 1);
    const float* src = hi + (size_t)bc * (HH * WH);
    float v00 = src[iy0 * WH + ix0], v01 = src[iy0 * WH + ix1];
    float v10 = src[iy1 * WH + ix0], v11 = src[iy1 * WH + ix1];
    out[idx] = (1.f - wx) * (1.f - wy) * v00 + wx * (1.f - wy) * v01
             + (1.f - wx) * wy * v10 + wx * wy * v11;
}

// ---------------- generic 1x1-conv GEMM -------------------------------
// Y[b,o,m] = sum_k W[o,k] * X(k)[b,m] (+bias) (+BN+ReLU if gamma!=null)
// X is the virtual concat of X0 (C0 ch) then X1 (C1 ch).
// Tiles: 128 (O) x 64 (M), BK=8, 256 threads, 8x4 microtile.
__global__ void __launch_bounds__(256) conv_gemm_kernel(
    const float* __restrict__ W, const float* __restrict__ bias,
    const float* __restrict__ X0, int C0,
    const float* __restrict__ X1, int C1,
    float* __restrict__ Y, int O,
    const float* __restrict__ gamma, const float* __restrict__ beta,
    const float* __restrict__ rmean, const float* __restrict__ rvar)
{
    const int M = NPIX;
    int b  = blockIdx.z;
    int m0 = blockIdx.x * 64;
    int o0 = blockIdx.y * 128;
    int K  = C0 + C1;
    int tid = threadIdx.x;
    int tx = tid & 15;          // m microtile (4 cols)
    int ty = tid >> 4;          // o microtile (8 rows)

    __shared__ float Ws[8][128];
    __shared__ float Xs[8][64];

    float acc[8][4];
    #pragma unroll
    for (int i = 0; i < 8; i++)
        #pragma unroll
        for (int j = 0; j < 4; j++) acc[i][j] = 0.f;

    int w_oo = tid & 127;          // 0..127
    int w_kb = (tid >> 7) * 4;     // 0 or 4
    int x_kk = tid >> 5;           // 0..7
    int x_mm = (tid & 31) * 2;     // 0..62 step 2

    for (int k0 = 0; k0 < K; k0 += 8) {
        float4 wv = make_float4(0.f, 0.f, 0.f, 0.f);
        if (o0 + w_oo < O)
            wv = *(const float4*)&W[(size_t)(o0 + w_oo) * K + k0 + w_kb];
        Ws[w_kb + 0][w_oo] = wv.x;
        Ws[w_kb + 1][w_oo] = wv.y;
        Ws[w_kb + 2][w_oo] = wv.z;
        Ws[w_kb + 3][w_oo] = wv.w;

        int k = k0 + x_kk;
        const float* xp = (k < C0) ? (X0 + (size_t)(b * C0 + k) * M)
                                   : (X1 + (size_t)(b * C1 + (k - C0)) * M);
        *(float2*)&Xs[x_kk][x_mm] = *(const float2*)&xp[m0 + x_mm];
        __syncthreads();

        #pragma unroll
        for (int kk = 0; kk < 8; kk++) {
            float4 a0 = *(const float4*)&Ws[kk][ty * 8];
            float4 a1 = *(const float4*)&Ws[kk][ty * 8 + 4];
            float4 xv = *(const float4*)&Xs[kk][tx * 4];
            float ar[8] = {a0.x, a0.y, a0.z, a0.w, a1.x, a1.y, a1.z, a1.w};
            float xr[4] = {xv.x, xv.y, xv.z, xv.w};
            #pragma unroll
            for (int i = 0; i < 8; i++)
                #pragma unroll
                for (int j = 0; j < 4; j++)
                    acc[i][j] += ar[i] * xr[j];
        }
        __syncthreads();
    }

    #pragma unroll
    for (int i = 0; i < 8; i++) {
        int o = o0 + ty * 8 + i;
        if (o >= O) break;
        float add = bias ? bias[o] : 0.f;
        float scale = 1.f, shift = add;
        bool bn = (gamma != nullptr);
        if (bn) {
            float inv = rsqrtf(rvar[o] + 1e-5f);
            scale = gamma[o] * inv;
            shift = (add - rmean[o]) * scale + beta[o];
        }
        float4 r;
        r.x = acc[i][0] * scale + shift;
        r.y = acc[i][1] * scale + shift;
        r.z = acc[i][2] * scale + shift;
        r.w = acc[i][3] * scale + shift;
        if (bn) {
            r.x = fmaxf(r.x, 0.f); r.y = fmaxf(r.y, 0.f);
            r.z = fmaxf(r.z, 0.f); r.w = fmaxf(r.w, 0.f);
        }
        *(float4*)&Y[(size_t)(b * O + o) * M + m0 + tx * 4] = r;
    }
}

// ---------------- channel-major -> NHWC for k and v --------------------
__global__ void transpose_kv_kernel() {
    int idx = blockIdx.x * blockDim.x + threadIdx.x;
    const int kt = NB * ITC * NPIX;
    const int vt = NB * INC * NPIX;
    if (idx < kt) {
        int n = idx & (NPIX - 1);
        int c = (idx >> 12) & (ITC - 1);
        int b = idx >> 16;
        g_kT[((size_t)b * NPIX + n) * ITC + c] = g_kcm[idx];
    } else {
        int t = idx - kt;
        if (t < vt) {
            int n = t & (NPIX - 1);
            int c = (t >> 12) & (INC - 1);
            int b = t >> 19;
            g_vT[((size_t)b * NPIX + n) * INC + c] = g_vcm[t];
        }
    }
}

// ---------------- deformable point attention ---------------------------
// one warp per query; phase1 lane=point, phase2 lane=4-channel group
__global__ void __launch_bounds__(256) attention_kernel() {
    __shared__ int   sIdx[8][128];
    __shared__ float sW  [8][128];
    int warp = threadIdx.x >> 5;
    int lane = threadIdx.x & 31;
    int gq = blockIdx.x * 8 + warp;          // 0..8191
    int b = gq >> 12;
    int n = gq & (NPIX - 1);

    // ---- phase 1: per-point sampling of k + logits ----
    float dx = g_off[((size_t)b * 64 + 2 * lane)     * NPIX + n];
    float dy = g_off[((size_t)b * 64 + 2 * lane + 1) * NPIX + n];
    float sx = (float)(n & 63) + dx;
    float sy = (float)(n >> 6) + dy;
    float x0f = floorf(sx), y0f = floorf(sy);
    float wx = sx - x0f,    wy = sy - y0f;
    int ix0 = min(max((int)x0f, 0), WL - 1);
    int ix1 = min(max((int)x0f + 1, 0), WL - 1);
    int iy0 = min(max((int)y0f, 0), HL - 1);
    int iy1 = min(max((int)y0f + 1, 0), HL - 1);
    int g00 = iy0 * WL + ix0, g01 = iy0 * WL + ix1;
    int g10 = iy1 * WL + ix0, g11 = iy1 * WL + ix1;
    float w00 = (1.f - wx) * (1.f - wy), w01 = wx * (1.f - wy);
    float w10 = (1.f - wx) * wy,         w11 = wx * wy;

    const float4* kb = (const float4*)(g_kT + (size_t)b * NPIX * ITC);
    const float*  qp = g_q + (size_t)b * ITC * NPIX + n;
    float logit = 0.f;
    #pragma unroll
    for (int cg = 0; cg < 4; cg++) {
        float4 v00 = kb[g00 * 4 + cg];
        float4 v01 = kb[g01 * 4 + cg];
        float4 v10 = kb[g10 * 4 + cg];
        float4 v11 = kb[g11 * 4 + cg];
        float ks0 = w00 * v00.x + w01 * v01.x + w10 * v10.x + w11 * v11.x;
        float ks1 = w00 * v00.y + w01 * v01.y + w10 * v10.y + w11 * v11.y;
        float ks2 = w00 * v00.z + w01 * v01.z + w10 * v10.z + w11 * v11.z;
        float ks3 = w00 * v00.w + w01 * v01.w + w10 * v10.w + w11 * v11.w;
        float q0 = qp[(size_t)(cg * 4 + 0) * NPIX];
        float q1 = qp[(size_t)(cg * 4 + 1) * NPIX];
        float q2 = qp[(size_t)(cg * 4 + 2) * NPIX];
        float q3 = qp[(size_t)(cg * 4 + 3) * NPIX];
        logit += q0 * ks0 + q1 * ks1 + q2 * ks2 + q3 * ks3;
    }
    logit *= 0.25f;   // 1/sqrt(16)

    // warp softmax over 32 points
    float mx = logit;
    #pragma unroll
    for (int s = 16; s; s >>= 1) mx = fmaxf(mx, __shfl_xor_sync(0xffffffffu, mx, s));
    float e = expf(logit - mx);
    float sum = e;
    #pragma unroll
    for (int s = 16; s; s >>= 1) sum += __shfl_xor_sync(0xffffffffu, sum, s);
    float attn = e / sum;

    sIdx[warp][lane * 4 + 0] = g00;  sW[warp][lane * 4 + 0] = attn * w00;
    sIdx[warp][lane * 4 + 1] = g01;  sW[warp][lane * 4 + 1] = attn * w01;
    sIdx[warp][lane * 4 + 2] = g10;  sW[warp][lane * 4 + 2] = attn * w10;
    sIdx[warp][lane * 4 + 3] = g11;  sW[warp][lane * 4 + 3] = attn * w11;
    __syncwarp();

    // ---- phase 2: weighted gather of v, lane = 4-channel group ----
    const float4* vb = (const float4*)(g_vT + (size_t)b * NPIX * INC);
    float4 acc = make_float4(0.f, 0.f, 0.f, 0.f);
    #pragma unroll 4
    for (int t = 0; t < 128; t++) {
        int g = sIdx[warp][t];
        float w = sW[warp][t];
        float4 vv = vb[g * 32 + lane];
        acc.x += w * vv.x;  acc.y += w * vv.y;
        acc.z += w * vv.z;  acc.w += w * vv.w;
    }
    float* outp = g_attn + ((size_t)b * INC + lane * 4) * NPIX + n;
    outp[0 * NPIX] = acc.x;
    outp[1 * NPIX] = acc.y;
    outp[2 * NPIX] = acc.z;
    outp[3 * NPIX] = acc.w;
}

// ---------------- launch ------------------------------------------------
extern "C" void kernel_launch(void* const* d_in, const int* in_sizes, int n_in,
                              void* d_out, int out_size) {
    const float* low   = (const float*)d_in[0];
    const float* high  = (const float*)d_in[1];
    const float* W1    = (const float*)d_in[2];
    const float* b1    = (const float*)d_in[3];
    const float* W2    = (const float*)d_in[4];
    const float* b2    = (const float*)d_in[5];
    const float* Wq    = (const float*)d_in[6];
    const float* bq    = (const float*)d_in[7];
    const float* Wk    = (const float*)d_in[8];
    const float* bk    = (const float*)d_in[9];
    const float* Wv    = (const float*)d_in[10];
    const float* bv    = (const float*)d_in[11];
    const float* Woff  = (const float*)d_in[12];
    const float* boff  = (const float*)d_in[13];
    const float* Wb    = (const float*)d_in[14];
    const float* gamma = (const float*)d_in[15];
    const float* beta  = (const float*)d_in[16];
    const float* rmean = (const float*)d_in[17];
    const float* rvar  = (const float*)d_in[18];
    float* out = (float*)d_out;

    float *hu, *qf, *vf, *qb, *ob, *kcm, *vcm;
    cudaGetSymbolAddress((void**)&hu,  g_high_up);
    cudaGetSymbolAddress((void**)&qf,  g_qf);
    cudaGetSymbolAddress((void**)&vf,  g_vf);
    cudaGetSymbolAddress((void**)&qb,  g_q);
    cudaGetSymbolAddress((void**)&ob,  g_off);
    cudaGetSymbolAddress((void**)&kcm, g_kcm);
    cudaGetSymbolAddress((void**)&vcm, g_vcm);

    // 1. upsample high -> high_up
    upsample_kernel<<<(NB * CH * NPIX + 255) / 256, 256>>>(high, hu);

    dim3 blk(256);
    // 2. qf = W1 @ concat(high_up, low) + b1    (O=128, K=512)
    conv_gemm_kernel<<<dim3(NPIX / 64, 1, NB), blk>>>(
        W1, b1, hu, CH, low, CH, qf, INC, nullptr, nullptr, nullptr, nullptr);
    // 3. vf = W2 @ high_up + b2                 (O=128, K=256)
    conv_gemm_kernel<<<dim3(NPIX / 64, 1, NB), blk>>>(
        W2, b2, hu, CH, nullptr, 0, vf, INC, nullptr, nullptr, nullptr, nullptr);
    // 4. q = Wq @ qf + bq                       (O=16, K=128)
    conv_gemm_kernel<<<dim3(NPIX / 64, 1, NB), blk>>>(
        Wq, bq, qf, INC, nullptr, 0, qb, ITC, nullptr, nullptr, nullptr, nullptr);
    // 5. off = Woff @ qf + boff                 (O=64, K=128)
    conv_gemm_kernel<<<dim3(NPIX / 64, 1, NB), blk>>>(
        Woff, boff, qf, INC, nullptr, 0, ob, 2 * NPT, nullptr, nullptr, nullptr, nullptr);
    // 6. k = Wk @ vf + bk                       (O=16, K=128)
    conv_gemm_kernel<<<dim3(NPIX / 64, 1, NB), blk>>>(
        Wk, bk, vf, INC, nullptr, 0, kcm, ITC, nullptr, nullptr, nullptr, nullptr);
    // 7. v = Wv @ vf + bv                       (O=128, K=128)
    conv_gemm_kernel<<<dim3(NPIX / 64, 1, NB), blk>>>(
        Wv, bv, vf, INC, nullptr, 0, vcm, INC, nullptr, nullptr, nullptr, nullptr);

    // 8. transpose k,v to NHWC
    {
        int tot = NB * ITC * NPIX + NB * INC * NPIX;
        transpose_kv_kernel<<<(tot + 255) / 256, 256>>>();
    }

    // 9. deformable attention (8192 queries, 8 per block)
    attention_kernel<<<NB * NPIX / 8, 256>>>();

    // 10. out = BN(ReLU epilogue)(Wb @ concat(attn, high_up))  (O=256, K=384)
    float* attn_ptr;
    cudaGetSymbolAddress((void**)&attn_ptr, g_attn);
    conv_gemm_kernel<<<dim3(NPIX / 64, 2, NB), blk>>>(
        Wb, nullptr, attn_ptr, INC, hu, CH, out, CH, gamma, beta, rmean, rvar);
}

// round 2
// speedup vs baseline: 1.3150x; 1.3150x over previous
#include <cuda_runtime.h>
#include <math.h>

// ---------------- problem constants ----------------
#define NB   2
#define CH   256
#define INC  128
#define ITC  16
#define NPT  32
#define HL   64
#define WL   64
#define NPIX 4096
#define HH   32
#define WH   32
#define MTOT (NB * NPIX)   // 8192 rows (batch folded into M)

// ---------------- scratch (__device__ globals, no allocs) ----------------
__device__ float g_cat1[MTOT * 512];   // [m][0:256)=high_up NHWC, [256:512)=low NHWC
__device__ float g_qf  [MTOT * 128];   // NHWC
__device__ float g_vf  [MTOT * 128];   // NHWC
__device__ float g_qoff[MTOT * 80];    // per pixel: q[16] | off[64]
__device__ float g_kv  [MTOT * 144];   // per pixel: k[16] | v[128]
__device__ float g_attn[MTOT * 128];   // NHWC
__device__ float g_Wg1[80 * 128];      // packed [Wq;Woff]
__device__ float g_Wg2[144 * 128];     // packed [Wk;Wv]
__device__ float g_bg1[80];
__device__ float g_bg2[144];

// ---------------- f32x2 helpers ----------------
__device__ __forceinline__ void ffma2(unsigned long long& d, unsigned long long a, unsigned long long b) {
    asm("fma.rn.f32x2 %0, %1, %2, %0;" : "+l"(d) : "l"(a), "l"(b));
}
__device__ __forceinline__ unsigned long long dup2(float x) {
    unsigned long long r;
    asm("mov.b64 %0, {%1, %1};" : "=l"(r) : "f"(x));
    return r;
}
__device__ __forceinline__ float lo32(unsigned long long v) { return __uint_as_float((unsigned)v); }
__device__ __forceinline__ float hi32(unsigned long long v) { return __uint_as_float((unsigned)(v >> 32)); }

// ---------------- prep: build cat1 (upsample + low transpose) + pack weights --
__global__ void __launch_bounds__(256) prep_kernel(
    const float* __restrict__ high, const float* __restrict__ low,
    const float* __restrict__ Wq, const float* __restrict__ bq,
    const float* __restrict__ Woff, const float* __restrict__ boff,
    const float* __restrict__ Wk, const float* __restrict__ bk,
    const float* __restrict__ Wv, const float* __restrict__ bv)
{
    int blk = blockIdx.x;
    int tid = threadIdx.x;

    if (blk >= 4096) {
        // weight / bias packing: 28896 elements over 64 blocks x 256 thr
        for (int e = (blk - 4096) * 256 + tid; e < 28896; e += 16384) {
            if (e < 10240) {
                int r = e >> 7, k = e & 127;
                g_Wg1[e] = (r < 16) ? Wq[r * 128 + k] : Woff[(r - 16) * 128 + k];
            } else if (e < 28672) {
                int t = e - 10240;
                int r = t >> 7, k = t & 127;
                g_Wg2[t] = (r < 16) ? Wk[r * 128 + k] : Wv[(r - 16) * 128 + k];
            } else if (e < 28752) {
                int i = e - 28672;
                g_bg1[i] = (i < 16) ? bq[i] : boff[i - 16];
            } else {
                int i = e - 28752;
                g_bg2[i] = (i < 16) ? bk[i] : bv[i - 16];
            }
        }
        return;
    }

    // NCHW -> NHWC tiles of 32 channels x 32 pixels via smem transpose
    int part = blk >> 11;          // 0: high_up, 1: low
    int r = blk & 2047;
    int b = r >> 10;
    int r2 = r & 1023;
    int pt = r2 >> 3;              // pixel tile 0..127
    int ct = r2 & 7;               // channel tile 0..7
    int p0 = pt * 32;
    int c0 = ct * 32;

    __shared__ float s[32][33];
    int px = tid & 31;
    int cq = tid >> 5;

    if (part == 1) {
        #pragma unroll
        for (int i = 0; i < 4; i++) {
            int c = cq * 4 + i;
            s[c][px] = low[((size_t)(b * CH + c0 + c)) * NPIX + p0 + px];
        }
    } else {
        // bilinear 2x upsample (half-pixel, border clamp). 32-pixel run = same y.
        int y = p0 >> 6;
        int xb = p0 & 63;
        float fy = y * 0.5f - 0.25f;
        float y0f = floorf(fy);
        float wy = fy - y0f;
        int iy0 = min(max((int)y0f, 0), HH - 1);
        int iy1 = min(max((int)y0f + 1, 0), HH - 1);
        int x = xb + px;
        float fx = x * 0.5f - 0.25f;
        float x0f = floorf(fx);
        float wx = fx - x0f;
        int ix0 = min(max((int)x0f, 0), WH - 1);
        int ix1 = min(max((int)x0f + 1, 0), WH - 1);
        #pragma unroll
        for (int i = 0; i < 4; i++) {
            int c = cq * 4 + i;
            const float* src = high + ((size_t)(b * CH + c0 + c)) * (HH * WH);
            float v00 = src[iy0 * WH + ix0], v01 = src[iy0 * WH + ix1];
            float v10 = src[iy1 * WH + ix0], v11 = src[iy1 * WH + ix1];
            s[c][px] = (1.f - wx) * (1.f - wy) * v00 + wx * (1.f - wy) * v01
                     + (1.f - wx) * wy * v10 + wx * wy * v11;
        }
    }
    __syncthreads();

    int cc = tid & 31;
    int pq = tid >> 5;
    int base_c = (part == 0 ? c0 : 256 + c0) + cc;
    #pragma unroll
    for (int i = 0; i < 4; i++) {
        int pp = pq * 4 + i;
        g_cat1[((size_t)(b * NPIX + p0 + pp)) * 512 + base_c] = s[cc][pp];
    }
}

// ---------------- f32x2 GEMM core ----------------
// Y[m][o] = sum_k Xrow(m)[k] * W[o][k], tile 128(M) x 64(N), BK=16, 256 thr
// Xrow(m)[k] = X0[m*ld0+k] for k<C0 else X1[m*ld1 + (k-C0)]
// mode 0: NHWC store (+bias); mode 1: channel-major store + BN + ReLU
#define TM 128
#define TN 64
#define BK 16

__device__ __forceinline__ void gemm_core(
    float* As, float* Bs,
    const float* __restrict__ W, const float* __restrict__ bias,
    int O, int K,
    const float* __restrict__ X0, int ld0, int C0,
    const float* __restrict__ X1, int ld1,
    float* __restrict__ Y, int ldy, int mode,
    const float* __restrict__ gamma, const float* __restrict__ beta,
    const float* __restrict__ rmean, const float* __restrict__ rvar,
    int m0, int n0)
{
    int tid = threadIdx.x;
    int mrow = tid & 127, khalf = tid >> 7;
    int nrow = tid & 63,  kq = tid >> 6;

    const float* xrow0 = X0 + (size_t)(m0 + mrow) * ld0;
    const float* xrow1 = X1 + (size_t)(m0 + mrow) * ld1 - C0;
    int o_load = n0 + nrow;
    bool ovalid = (o_load < O);
    const float* wrow = W + (size_t)(ovalid ? o_load : 0) * K;

    float4 ra0, ra1, rb;

    auto LDG = [&](int k0) {
        int k = k0 + khalf * 8;
        const float* p0 = (k < C0) ? xrow0 : xrow1;
        ra0 = *(const float4*)&p0[k];
        const float* p1 = (k + 4 < C0) ? xrow0 : xrow1;
        ra1 = *(const float4*)&p1[k + 4];
        rb = ovalid ? *(const float4*)&wrow[k0 + kq * 4] : make_float4(0.f, 0.f, 0.f, 0.f);
    };
    auto STS = [&](int buf) {
        float* ab = As + buf * (BK * TM);
        int kb = khalf * 8;
        ab[(kb + 0) * TM + mrow] = ra0.x;
        ab[(kb + 1) * TM + mrow] = ra0.y;
        ab[(kb + 2) * TM + mrow] = ra0.z;
        ab[(kb + 3) * TM + mrow] = ra0.w;
        ab[(kb + 4) * TM + mrow] = ra1.x;
        ab[(kb + 5) * TM + mrow] = ra1.y;
        ab[(kb + 6) * TM + mrow] = ra1.z;
        ab[(kb + 7) * TM + mrow] = ra1.w;
        float* bbuf = Bs + buf * (BK * TN);
        bbuf[(kq * 4 + 0) * TN + nrow] = rb.x;
        bbuf[(kq * 4 + 1) * TN + nrow] = rb.y;
        bbuf[(kq * 4 + 2) * TN + nrow] = rb.z;
        bbuf[(kq * 4 + 3) * TN + nrow] = rb.w;
    };

    int tx = tid & 15, ty = tid >> 4;
    unsigned long long acc[4][4];
    #pragma unroll
    for (int i = 0; i < 4; i++)
        #pragma unroll
        for (int j = 0; j < 4; j++) acc[i][j] = 0ULL;

    int nk = K / BK;
    LDG(0);
    STS(0);
    __syncthreads();

    for (int t = 0; t < nk; t++) {
        if (t + 1 < nk) LDG((t + 1) * BK);
        int buf = t & 1;
        const float* ab = As + buf * (BK * TM);
        const float* bbuf = Bs + buf * (BK * TN);
        #pragma unroll
        for (int kk = 0; kk < BK; kk++) {
            const unsigned long long* Ap =
                (const unsigned long long*)(ab + kk * TM + ty * 8);
            unsigned long long a0 = Ap[0], a1 = Ap[1], a2 = Ap[2], a3 = Ap[3];
            const float* bp = bbuf + kk * TN + tx * 4;
            unsigned long long b0 = dup2(bp[0]);
            unsigned long long b1 = dup2(bp[1]);
            unsigned long long b2 = dup2(bp[2]);
            unsigned long long b3 = dup2(bp[3]);
            ffma2(acc[0][0], a0, b0); ffma2(acc[0][1], a0, b1);
            ffma2(acc[0][2], a0, b2); ffma2(acc[0][3], a0, b3);
            ffma2(acc[1][0], a1, b0); ffma2(acc[1][1], a1, b1);
            ffma2(acc[1][2], a1, b2); ffma2(acc[1][3], a1, b3);
            ffma2(acc[2][0], a2, b0); ffma2(acc[2][1], a2, b1);
            ffma2(acc[2][2], a2, b2); ffma2(acc[2][3], a2, b3);
            ffma2(acc[3][0], a3, b0); ffma2(acc[3][1], a3, b1);
            ffma2(acc[3][2], a3, b2); ffma2(acc[3][3], a3, b3);
        }
        if (t + 1 < nk) {
            STS(buf ^ 1);
            __syncthreads();
        }
    }

    if (mode == 0) {
        int oc = n0 + tx * 4;
        if (oc < O) {
            float bx = bias ? bias[oc + 0] : 0.f;
            float by = bias ? bias[oc + 1] : 0.f;
            float bz = bias ? bias[oc + 2] : 0.f;
            float bw = bias ? bias[oc + 3] : 0.f;
            #pragma unroll
            for (int i = 0; i < 4; i++) {
                int m = m0 + ty * 8 + i * 2;
                float4 r0, r1;
                r0.x = lo32(acc[i][0]) + bx; r0.y = lo32(acc[i][1]) + by;
                r0.z = lo32(acc[i][2]) + bz; r0.w = lo32(acc[i][3]) + bw;
                r1.x = hi32(acc[i][0]) + bx; r1.y = hi32(acc[i][1]) + by;
                r1.z = hi32(acc[i][2]) + bz; r1.w = hi32(acc[i][3]) + bw;
                *(float4*)&Y[(size_t)m * ldy + oc] = r0;
                *(float4*)&Y[(size_t)(m + 1) * ldy + oc] = r1;
            }
        }
    } else {
        // channel-major [B][O][NPIX] with BN + ReLU
        int bidx = m0 >> 12;
        int mloc = (m0 & 4095) + ty * 8;
        #pragma unroll
        for (int j = 0; j < 4; j++) {
            int oc = n0 + tx * 4 + j;
            float inv = rsqrtf(rvar[oc] + 1e-5f);
            float sc = gamma[oc] * inv;
            float sh = beta[oc] - rmean[oc] * sc;
            float v[8];
            #pragma unroll
            for (int i = 0; i < 4; i++) {
                v[2 * i]     = fmaxf(lo32(acc[i][j]) * sc + sh, 0.f);
                v[2 * i + 1] = fmaxf(hi32(acc[i][j]) * sc + sh, 0.f);
            }
            float* yp = Y + ((size_t)(bidx * O + oc)) * NPIX + mloc;
            *(float4*)yp       = make_float4(v[0], v[1], v[2], v[3]);
            *(float4*)(yp + 4) = make_float4(v[4], v[5], v[6], v[7]);
        }
    }
}

// ---------------- GEMM stage kernels ----------------
__global__ void __launch_bounds__(256) gemm_stage1(
    const float* __restrict__ W1, const float* __restrict__ b1,
    const float* __restrict__ W2, const float* __restrict__ b2)
{
    __shared__ float As[2 * BK * TM];
    __shared__ float Bs[2 * BK * TN];
    int m0 = blockIdx.x * TM;
    int by = blockIdx.y;
    if (by < 2)
        gemm_core(As, Bs, W1, b1, 128, 512, g_cat1, 512, 512, g_cat1, 512,
                  g_qf, 128, 0, 0, 0, 0, 0, m0, by * 64);
    else
        gemm_core(As, Bs, W2, b2, 128, 256, g_cat1, 512, 256, g_cat1, 512,
                  g_vf, 128, 0, 0, 0, 0, 0, m0, (by - 2) * 64);
}

__global__ void __launch_bounds__(256) gemm_stage2()
{
    __shared__ float As[2 * BK * TM];
    __shared__ float Bs[2 * BK * TN];
    int m0 = blockIdx.x * TM;
    int by = blockIdx.y;
    if (by < 2)
        gemm_core(As, Bs, g_Wg1, g_bg1, 80, 128, g_qf, 128, 128, g_qf, 128,
                  g_qoff, 80, 0, 0, 0, 0, 0, m0, by * 64);
    else
        gemm_core(As, Bs, g_Wg2, g_bg2, 144, 128, g_vf, 128, 128, g_vf, 128,
                  g_kv, 144, 0, 0, 0, 0, 0, m0, (by - 2) * 64);
}

__global__ void __launch_bounds__(256) gemm_stage3(
    const float* __restrict__ Wb,
    const float* __restrict__ gamma, const float* __restrict__ beta,
    const float* __restrict__ rmean, const float* __restrict__ rvar,
    float* __restrict__ out)
{
    __shared__ float As[2 * BK * TM];
    __shared__ float Bs[2 * BK * TN];
    int m0 = blockIdx.x * TM;
    int by = blockIdx.y;
    gemm_core(As, Bs, Wb, nullptr, 256, 384, g_attn, 128, 128, g_cat1, 512,
              out, 0, 1, gamma, beta, rmean, rvar, m0, by * 64);
}

// ---------------- deformable point attention ----------------
__global__ void __launch_bounds__(256) attention_kernel()
{
    __shared__ int   sIdx[8][128];
    __shared__ float sW  [8][128];
    int warp = threadIdx.x >> 5;
    int lane = threadIdx.x & 31;
    int m = blockIdx.x * 8 + warp;
    int b = m >> 12;
    int n = m & (NPIX - 1);

    const float* row = g_qoff + (size_t)m * 80;
    float dx = row[16 + 2 * lane];
    float dy = row[17 + 2 * lane];
    float sx = (float)(n & 63) + dx;
    float sy = (float)(n >> 6) + dy;
    float x0f = floorf(sx), y0f = floorf(sy);
    float wx = sx - x0f,    wy = sy - y0f;
    int ix0 = min(max((int)x0f, 0), WL - 1);
    int ix1 = min(max((int)x0f + 1, 0), WL - 1);
    int iy0 = min(max((int)y0f, 0), HL - 1);
    int iy1 = min(max((int)y0f + 1, 0), HL - 1);
    int g00 = iy0 * WL + ix0, g01 = iy0 * WL + ix1;
    int g10 = iy1 * WL + ix0, g11 = iy1 * WL + ix1;
    float w00 = (1.f - wx) * (1.f - wy), w01 = wx * (1.f - wy);
    float w10 = (1.f - wx) * wy,         w11 = wx * wy;

    const float* kvb = g_kv + (size_t)b * NPIX * 144;
    const float4* qp = (const float4*)row;
    float4 q0 = qp[0], q1 = qp[1], q2 = qp[2], q3 = qp[3];
    float4 qv[4] = {q0, q1, q2, q3};

    float logit = 0.f;
    #pragma unroll
    for (int cg = 0; cg < 4; cg++) {
        float4 v00 = *(const float4*)(kvb + (size_t)g00 * 144 + cg * 4);
        float4 v01 = *(const float4*)(kvb + (size_t)g01 * 144 + cg * 4);
        float4 v10 = *(const float4*)(kvb + (size_t)g10 * 144 + cg * 4);
        float4 v11 = *(const float4*)(kvb + (size_t)g11 * 144 + cg * 4);
        float k0 = w00 * v00.x + w01 * v01.x + w10 * v10.x + w11 * v11.x;
        float k1 = w00 * v00.y + w01 * v01.y + w10 * v10.y + w11 * v11.y;
        float k2 = w00 * v00.z + w01 * v01.z + w10 * v10.z + w11 * v11.z;
        float k3 = w00 * v00.w + w01 * v01.w + w10 * v10.w + w11 * v11.w;
        logit += qv[cg].x * k0 + qv[cg].y * k1 + qv[cg].z * k2 + qv[cg].w * k3;
    }
    logit *= 0.25f;   // 1/sqrt(16)

    float mx = logit;
    #pragma unroll
    for (int s = 16; s; s >>= 1) mx = fmaxf(mx, __shfl_xor_sync(0xffffffffu, mx, s));
    float e = expf(logit - mx);
    float sum = e;
    #pragma unroll
    for (int s = 16; s; s >>= 1) sum += __shfl_xor_sync(0xffffffffu, sum, s);
    float attn = e / sum;

    sIdx[warp][lane * 4 + 0] = g00;  sW[warp][lane * 4 + 0] = attn * w00;
    sIdx[warp][lane * 4 + 1] = g01;  sW[warp][lane * 4 + 1] = attn * w01;
    sIdx[warp][lane * 4 + 2] = g10;  sW[warp][lane * 4 + 2] = attn * w10;
    sIdx[warp][lane * 4 + 3] = g11;  sW[warp][lane * 4 + 3] = attn * w11;
    __syncwarp();

    float4 acc = make_float4(0.f, 0.f, 0.f, 0.f);
    #pragma unroll 4
    for (int t = 0; t < 128; t++) {
        int g = sIdx[warp][t];
        float w = sW[warp][t];
        float4 vv = *(const float4*)(kvb + (size_t)g * 144 + 16 + lane * 4);
        acc.x += w * vv.x;  acc.y += w * vv.y;
        acc.z += w * vv.z;  acc.w += w * vv.w;
    }
    *(float4*)(g_attn + (size_t)m * 128 + lane * 4) = acc;
}

// ---------------- launch ------------------------------------------------
extern "C" void kernel_launch(void* const* d_in, const int* in_sizes, int n_in,
                              void* d_out, int out_size) {
    const float* low   = (const float*)d_in[0];
    const float* high  = (const float*)d_in[1];
    const float* W1    = (const float*)d_in[2];
    const float* b1    = (const float*)d_in[3];
    const float* W2    = (const float*)d_in[4];
    const float* b2    = (const float*)d_in[5];
    const float* Wq    = (const float*)d_in[6];
    const float* bq    = (const float*)d_in[7];
    const float* Wk    = (const float*)d_in[8];
    const float* bk    = (const float*)d_in[9];
    const float* Wv    = (const float*)d_in[10];
    const float* bv    = (const float*)d_in[11];
    const float* Woff  = (const float*)d_in[12];
    const float* boff  = (const float*)d_in[13];
    const float* Wb    = (const float*)d_in[14];
    const float* gamma = (const float*)d_in[15];
    const float* beta  = (const float*)d_in[16];
    const float* rmean = (const float*)d_in[17];
    const float* rvar  = (const float*)d_in[18];
    float* out = (float*)d_out;

    prep_kernel<<<4160, 256>>>(high, low, Wq, bq, Woff, boff, Wk, bk, Wv, bv);
    gemm_stage1<<<dim3(64, 4), 256>>>(W1, b1, W2, b2);
    gemm_stage2<<<dim3(64, 5), 256>>>();
    attention_kernel<<<MTOT / 8, 256>>>();
    gemm_stage3<<<dim3(64, 4), 256>>>(Wb, gamma, beta, rmean, rvar, out);
}

// round 3
// speedup vs baseline: 1.3683x; 1.0405x over previous
#include <cuda_runtime.h>
#include <math.h>

// ---------------- problem constants ----------------
#define NB   2
#define CH   256
#define INC  128
#define ITC  16
#define NPT  32
#define HL   64
#define WL   64
#define NPIX 4096
#define HH   32
#define WH   32
#define MTOT (NB * NPIX)   // 8192 rows (batch folded into M)

// ---------------- scratch (__device__ globals, no allocs) ----------------
__device__ float g_cat1[MTOT * 512];   // [m][0:256)=high_up NHWC, [256:512)=low NHWC
__device__ float g_qf  [MTOT * 128];   // NHWC
__device__ float g_vf  [MTOT * 128];   // NHWC
__device__ float g_qoff[MTOT * 80];    // per pixel: q[16] | off[64]
__device__ float g_kv  [MTOT * 144];   // per pixel: k[16] | v[128]
__device__ float g_attn[MTOT * 128];   // NHWC
__device__ float g_Wg1[80 * 128];      // packed [Wq;Woff]
__device__ float g_Wg2[144 * 128];     // packed [Wk;Wv]
__device__ float g_bg1[80];
__device__ float g_bg2[144];

// ---------------- f32x2 helpers ----------------
__device__ __forceinline__ void ffma2(unsigned long long& d, unsigned long long a, unsigned long long b) {
    asm("fma.rn.f32x2 %0, %1, %2, %0;" : "+l"(d) : "l"(a), "l"(b));
}
__device__ __forceinline__ unsigned long long dup2(float x) {
    unsigned long long r;
    asm("mov.b64 %0, {%1, %1};" : "=l"(r) : "f"(x));
    return r;
}
__device__ __forceinline__ float lo32(unsigned long long v) { return __uint_as_float((unsigned)v); }
__device__ __forceinline__ float hi32(unsigned long long v) { return __uint_as_float((unsigned)(v >> 32)); }

// ---------------- prep: build cat1 (upsample + low transpose) + pack weights --
__global__ void __launch_bounds__(256) prep_kernel(
    const float* __restrict__ high, const float* __restrict__ low,
    const float* __restrict__ Wq, const float* __restrict__ bq,
    const float* __restrict__ Woff, const float* __restrict__ boff,
    const float* __restrict__ Wk, const float* __restrict__ bk,
    const float* __restrict__ Wv, const float* __restrict__ bv)
{
    int blk = blockIdx.x;
    int tid = threadIdx.x;

    if (blk >= 4096) {
        for (int e = (blk - 4096) * 256 + tid; e < 28896; e += 16384) {
            if (e < 10240) {
                int r = e >> 7, k = e & 127;
                g_Wg1[e] = (r < 16) ? Wq[r * 128 + k] : Woff[(r - 16) * 128 + k];
            } else if (e < 28672) {
                int t = e - 10240;
                int r = t >> 7, k = t & 127;
                g_Wg2[t] = (r < 16) ? Wk[r * 128 + k] : Wv[(r - 16) * 128 + k];
            } else if (e < 28752) {
                int i = e - 28672;
                g_bg1[i] = (i < 16) ? bq[i] : boff[i - 16];
            } else {
                int i = e - 28752;
                g_bg2[i] = (i < 16) ? bk[i] : bv[i - 16];
            }
        }
        return;
    }

    // NCHW -> NHWC tiles of 32 channels x 32 pixels via smem transpose
    int part = blk >> 11;          // 0: high_up, 1: low
    int r = blk & 2047;
    int b = r >> 10;
    int r2 = r & 1023;
    int pt = r2 >> 3;              // pixel tile 0..127
    int ct = r2 & 7;               // channel tile 0..7
    int p0 = pt * 32;
    int c0 = ct * 32;

    __shared__ float s[32][33];
    int px = tid & 31;
    int cq = tid >> 5;

    if (part == 1) {
        #pragma unroll
        for (int i = 0; i < 4; i++) {
            int c = cq * 4 + i;
            s[c][px] = low[((size_t)(b * CH + c0 + c)) * NPIX + p0 + px];
        }
    } else {
        int y = p0 >> 6;
        int xb = p0 & 63;
        float fy = y * 0.5f - 0.25f;
        float y0f = floorf(fy);
        float wy = fy - y0f;
        int iy0 = min(max((int)y0f, 0), HH - 1);
        int iy1 = min(max((int)y0f + 1, 0), HH - 1);
        int x = xb + px;
        float fx = x * 0.5f - 0.25f;
        float x0f = floorf(fx);
        float wx = fx - x0f;
        int ix0 = min(max((int)x0f, 0), WH - 1);
        int ix1 = min(max((int)x0f + 1, 0), WH - 1);
        #pragma unroll
        for (int i = 0; i < 4; i++) {
            int c = cq * 4 + i;
            const float* src = high + ((size_t)(b * CH + c0 + c)) * (HH * WH);
            float v00 = src[iy0 * WH + ix0], v01 = src[iy0 * WH + ix1];
            float v10 = src[iy1 * WH + ix0], v11 = src[iy1 * WH + ix1];
            s[c][px] = (1.f - wx) * (1.f - wy) * v00 + wx * (1.f - wy) * v01
                     + (1.f - wx) * wy * v10 + wx * wy * v11;
        }
    }
    __syncthreads();

    int cc = tid & 31;
    int pq = tid >> 5;
    int base_c = (part == 0 ? c0 : 256 + c0) + cc;
    #pragma unroll
    for (int i = 0; i < 4; i++) {
        int pp = pq * 4 + i;
        g_cat1[((size_t)(b * NPIX + p0 + pp)) * 512 + base_c] = s[cc][pp];
    }
}

// ---------------- f32x2 GEMM core ----------------
#define TM 128
#define TN 64
#define BK 16

__device__ __forceinline__ void gemm_core(
    float* As, float* Bs,
    const float* __restrict__ W, const float* __restrict__ bias,
    int O, int K,
    const float* __restrict__ X0, int ld0, int C0,
    const float* __restrict__ X1, int ld1,
    float* __restrict__ Y, int ldy, int mode,
    const float* __restrict__ gamma, const float* __restrict__ beta,
    const float* __restrict__ rmean, const float* __restrict__ rvar,
    int m0, int n0)
{
    int tid = threadIdx.x;
    int mrow = tid & 127, khalf = tid >> 7;
    int nrow = tid & 63,  kq = tid >> 6;

    const float* xrow0 = X0 + (size_t)(m0 + mrow) * ld0;
    const float* xrow1 = X1 + (size_t)(m0 + mrow) * ld1 - C0;
    int o_load = n0 + nrow;
    bool ovalid = (o_load < O);
    const float* wrow = W + (size_t)(ovalid ? o_load : 0) * K;

    float4 ra0, ra1, rb;

    auto LDG = [&](int k0) {
        int k = k0 + khalf * 8;
        const float* p0 = (k < C0) ? xrow0 : xrow1;
        ra0 = *(const float4*)&p0[k];
        const float* p1 = (k + 4 < C0) ? xrow0 : xrow1;
        ra1 = *(const float4*)&p1[k + 4];
        rb = ovalid ? *(const float4*)&wrow[k0 + kq * 4] : make_float4(0.f, 0.f, 0.f, 0.f);
    };
    auto STS = [&](int buf) {
        float* ab = As + buf * (BK * TM);
        int kb = khalf * 8;
        ab[(kb + 0) * TM + mrow] = ra0.x;
        ab[(kb + 1) * TM + mrow] = ra0.y;
        ab[(kb + 2) * TM + mrow] = ra0.z;
        ab[(kb + 3) * TM + mrow] = ra0.w;
        ab[(kb + 4) * TM + mrow] = ra1.x;
        ab[(kb + 5) * TM + mrow] = ra1.y;
        ab[(kb + 6) * TM + mrow] = ra1.z;
        ab[(kb + 7) * TM + mrow] = ra1.w;
        float* bbuf = Bs + buf * (BK * TN);
        bbuf[(kq * 4 + 0) * TN + nrow] = rb.x;
        bbuf[(kq * 4 + 1) * TN + nrow] = rb.y;
        bbuf[(kq * 4 + 2) * TN + nrow] = rb.z;
        bbuf[(kq * 4 + 3) * TN + nrow] = rb.w;
    };

    int tx = tid & 15, ty = tid >> 4;
    unsigned long long acc[4][4];
    #pragma unroll
    for (int i = 0; i < 4; i++)
        #pragma unroll
        for (int j = 0; j < 4; j++) acc[i][j] = 0ULL;

    int nk = K / BK;
    LDG(0);
    STS(0);
    __syncthreads();

    for (int t = 0; t < nk; t++) {
        if (t + 1 < nk) LDG((t + 1) * BK);
        int buf = t & 1;
        const float* ab = As + buf * (BK * TM);
        const float* bbuf = Bs + buf * (BK * TN);
        #pragma unroll
        for (int kk = 0; kk < BK; kk++) {
            const unsigned long long* Ap =
                (const unsigned long long*)(ab + kk * TM + ty * 8);
            unsigned long long a0 = Ap[0], a1 = Ap[1], a2 = Ap[2], a3 = Ap[3];
            const float* bp = bbuf + kk * TN + tx * 4;
            unsigned long long b0 = dup2(bp[0]);
            unsigned long long b1 = dup2(bp[1]);
            unsigned long long b2 = dup2(bp[2]);
            unsigned long long b3 = dup2(bp[3]);
            ffma2(acc[0][0], a0, b0); ffma2(acc[0][1], a0, b1);
            ffma2(acc[0][2], a0, b2); ffma2(acc[0][3], a0, b3);
            ffma2(acc[1][0], a1, b0); ffma2(acc[1][1], a1, b1);
            ffma2(acc[1][2], a1, b2); ffma2(acc[1][3], a1, b3);
            ffma2(acc[2][0], a2, b0); ffma2(acc[2][1], a2, b1);
            ffma2(acc[2][2], a2, b2); ffma2(acc[2][3], a2, b3);
            ffma2(acc[3][0], a3, b0); ffma2(acc[3][1], a3, b1);
            ffma2(acc[3][2], a3, b2); ffma2(acc[3][3], a3, b3);
        }
        if (t + 1 < nk) {
            STS(buf ^ 1);
            __syncthreads();
        }
    }

    if (mode == 0) {
        int oc = n0 + tx * 4;
        if (oc < O) {
            float bx = bias ? bias[oc + 0] : 0.f;
            float by = bias ? bias[oc + 1] : 0.f;
            float bz = bias ? bias[oc + 2] : 0.f;
            float bw = bias ? bias[oc + 3] : 0.f;
            #pragma unroll
            for (int i = 0; i < 4; i++) {
                int m = m0 + ty * 8 + i * 2;
                float4 r0, r1;
                r0.x = lo32(acc[i][0]) + bx; r0.y = lo32(acc[i][1]) + by;
                r0.z = lo32(acc[i][2]) + bz; r0.w = lo32(acc[i][3]) + bw;
                r1.x = hi32(acc[i][0]) + bx; r1.y = hi32(acc[i][1]) + by;
                r1.z = hi32(acc[i][2]) + bz; r1.w = hi32(acc[i][3]) + bw;
                *(float4*)&Y[(size_t)m * ldy + oc] = r0;
                *(float4*)&Y[(size_t)(m + 1) * ldy + oc] = r1;
            }
        }
    } else {
        int bidx = m0 >> 12;
        int mloc = (m0 & 4095) + ty * 8;
        #pragma unroll
        for (int j = 0; j < 4; j++) {
            int oc = n0 + tx * 4 + j;
            float inv = rsqrtf(rvar[oc] + 1e-5f);
            float sc = gamma[oc] * inv;
            float sh = beta[oc] - rmean[oc] * sc;
            float v[8];
            #pragma unroll
            for (int i = 0; i < 4; i++) {
                v[2 * i]     = fmaxf(lo32(acc[i][j]) * sc + sh, 0.f);
                v[2 * i + 1] = fmaxf(hi32(acc[i][j]) * sc + sh, 0.f);
            }
            float* yp = Y + ((size_t)(bidx * O + oc)) * NPIX + mloc;
            *(float4*)yp       = make_float4(v[0], v[1], v[2], v[3]);
            *(float4*)(yp + 4) = make_float4(v[4], v[5], v[6], v[7]);
        }
    }
}

// ---------------- GEMM stage kernels ----------------
__global__ void __launch_bounds__(256) gemm_stage1(
    const float* __restrict__ W1, const float* __restrict__ b1,
    const float* __restrict__ W2, const float* __restrict__ b2)
{
    __shared__ float As[2 * BK * TM];
    __shared__ float Bs[2 * BK * TN];
    int m0 = blockIdx.x * TM;
    int by = blockIdx.y;
    if (by < 2)
        gemm_core(As, Bs, W1, b1, 128, 512, g_cat1, 512, 512, g_cat1, 512,
                  g_qf, 128, 0, 0, 0, 0, 0, m0, by * 64);
    else
        gemm_core(As, Bs, W2, b2, 128, 256, g_cat1, 512, 256, g_cat1, 512,
                  g_vf, 128, 0, 0, 0, 0, 0, m0, (by - 2) * 64);
}

__global__ void __launch_bounds__(256) gemm_stage2()
{
    __shared__ float As[2 * BK * TM];
    __shared__ float Bs[2 * BK * TN];
    int m0 = blockIdx.x * TM;
    int by = blockIdx.y;
    if (by < 2)
        gemm_core(As, Bs, g_Wg1, g_bg1, 80, 128, g_qf, 128, 128, g_qf, 128,
                  g_qoff, 80, 0, 0, 0, 0, 0, m0, by * 64);
    else
        gemm_core(As, Bs, g_Wg2, g_bg2, 144, 128, g_vf, 128, 128, g_vf, 128,
                  g_kv, 144, 0, 0, 0, 0, 0, m0, (by - 2) * 64);
}

__global__ void __launch_bounds__(256) gemm_stage3(
    const float* __restrict__ Wb,
    const float* __restrict__ gamma, const float* __restrict__ beta,
    const float* __restrict__ rmean, const float* __restrict__ rvar,
    float* __restrict__ out)
{
    __shared__ float As[2 * BK * TM];
    __shared__ float Bs[2 * BK * TN];
    int m0 = blockIdx.x * TM;
    int by = blockIdx.y;
    gemm_core(As, Bs, Wb, nullptr, 256, 384, g_attn, 128, 128, g_cat1, 512,
              out, 0, 1, gamma, beta, rmean, rvar, m0, by * 64);
}

// ---------------- deformable point attention (restructured) -------------
// one warp per query.
// Phase 1: lane = (point-octet, channel-quad). Tap indices/weights shfl'd
//          from the owning lane -> each k LDG touches ~8 lines, not ~28.
// Phase 2: lane = channel-quad; 128-tap weighted gather of v rows.
__global__ void __launch_bounds__(256) attention_kernel()
{
    __shared__ int   sIdx[8][128];
    __shared__ float sW  [8][128];
    __shared__ float sAttn[8][32];
    int warp = threadIdx.x >> 5;
    int lane = threadIdx.x & 31;
    int m = blockIdx.x * 8 + warp;
    int b = m >> 12;
    int n = m & (NPIX - 1);

    const float* row = g_qoff + (size_t)m * 80;

    // ---- per-lane (point = lane) offsets -> 4 taps ----
    float2 d = *(const float2*)(row + 16 + 2 * lane);
    float sx = (float)(n & 63) + d.x;
    float sy = (float)(n >> 6) + d.y;
    float x0f = floorf(sx), y0f = floorf(sy);
    float wx = sx - x0f,    wy = sy - y0f;
    int ix0 = min(max((int)x0f, 0), WL - 1);
    int ix1 = min(max((int)x0f + 1, 0), WL - 1);
    int iy0 = min(max((int)y0f, 0), HL - 1);
    int iy1 = min(max((int)y0f + 1, 0), HL - 1);
    // tap indices in float4-row units (row stride = 144 floats = 36 float4)
    int g00 = (iy0 * WL + ix0) * 36, g01 = (iy0 * WL + ix1) * 36;
    int g10 = (iy1 * WL + ix0) * 36, g11 = (iy1 * WL + ix1) * 36;
    float w00 = (1.f - wx) * (1.f - wy), w01 = wx * (1.f - wy);
    float w10 = (1.f - wx) * wy,         w11 = wx * wy;

    int cq = lane & 3;              // channel quad
    int oct = lane >> 2;            // point octet index
    float4 qv = *(const float4*)(row + 4 * cq);
    const float4* kvb = (const float4*)(g_kv + (size_t)b * NPIX * 144);

    float logit[4];
    #pragma unroll
    for (int g = 0; g < 4; g++) {
        int src = oct + 8 * g;      // point handled this iteration
        int G0 = __shfl_sync(0xffffffffu, g00, src);
        int G1 = __shfl_sync(0xffffffffu, g01, src);
        int G2 = __shfl_sync(0xffffffffu, g10, src);
        int G3 = __shfl_sync(0xffffffffu, g11, src);
        float W0 = __shfl_sync(0xffffffffu, w00, src);
        float W1 = __shfl_sync(0xffffffffu, w01, src);
        float W2 = __shfl_sync(0xffffffffu, w10, src);
        float W3 = __shfl_sync(0xffffffffu, w11, src);
        float4 k0 = kvb[G0 + cq];
        float4 k1 = kvb[G1 + cq];
        float4 k2 = kvb[G2 + cq];
        float4 k3 = kvb[G3 + cq];
        float ksx = W0 * k0.x + W1 * k1.x + W2 * k2.x + W3 * k3.x;
        float ksy = W0 * k0.y + W1 * k1.y + W2 * k2.y + W3 * k3.y;
        float ksz = W0 * k0.z + W1 * k1.z + W2 * k2.z + W3 * k3.z;
        float ksw = W0 * k0.w + W1 * k1.w + W2 * k2.w + W3 * k3.w;
        float part = qv.x * ksx + qv.y * ksy + qv.z * ksz + qv.w * ksw;
        part += __shfl_xor_sync(0xffffffffu, part, 1);
        part += __shfl_xor_sync(0xffffffffu, part, 2);
        logit[g] = part * 0.25f;   // 1/sqrt(16)
        // quad-lane cq writes tap cq of point src
        int   Gq = (cq == 0) ? G0 : (cq == 1) ? G1 : (cq == 2) ? G2 : G3;
        float Wq = (cq == 0) ? W0 : (cq == 1) ? W1 : (cq == 2) ? W2 : W3;
        sIdx[warp][src * 4 + cq] = Gq;
        sW  [warp][src * 4 + cq] = Wq;
    }

    // ---- softmax over 32 points (values replicated across each quad) ----
    float mx = fmaxf(fmaxf(logit[0], logit[1]), fmaxf(logit[2], logit[3]));
    mx = fmaxf(mx, __shfl_xor_sync(0xffffffffu, mx, 4));
    mx = fmaxf(mx, __shfl_xor_sync(0xffffffffu, mx, 8));
    mx = fmaxf(mx, __shfl_xor_sync(0xffffffffu, mx, 16));
    float e0 = expf(logit[0] - mx), e1 = expf(logit[1] - mx);
    float e2 = expf(logit[2] - mx), e3 = expf(logit[3] - mx);
    float sum = e0 + e1 + e2 + e3;
    sum += __shfl_xor_sync(0xffffffffu, sum, 4);
    sum += __shfl_xor_sync(0xffffffffu, sum, 8);
    sum += __shfl_xor_sync(0xffffffffu, sum, 16);
    float inv = 1.f / sum;
    if (cq == 0) {
        sAttn[warp][oct + 0]  = e0 * inv;
        sAttn[warp][oct + 8]  = e1 * inv;
        sAttn[warp][oct + 16] = e2 * inv;
        sAttn[warp][oct + 24] = e3 * inv;
    }
    __syncwarp();

    // ---- fold attn into tap weights (lane = point) ----
    {
        float a = sAttn[warp][lane];
        float4 w4 = *(float4*)&sW[warp][lane * 4];
        w4.x *= a; w4.y *= a; w4.z *= a; w4.w *= a;
        *(float4*)&sW[warp][lane * 4] = w4;
    }
    __syncwarp();

    // ---- phase 2: weighted gather of v rows (lane = channel quad) ----
    float4 acc = make_float4(0.f, 0.f, 0.f, 0.f);
    #pragma unroll 2
    for (int t = 0; t < 128; t += 4) {
        int4   i4 = *(const int4*)&sIdx[warp][t];
        float4 w4 = *(const float4*)&sW[warp][t];
        float4 v0 = kvb[i4.x + 4 + lane];
        float4 v1 = kvb[i4.y + 4 + lane];
        float4 v2 = kvb[i4.z + 4 + lane];
        float4 v3 = kvb[i4.w + 4 + lane];
        acc.x += w4.x * v0.x + w4.y * v1.x + w4.z * v2.x + w4.w * v3.x;
        acc.y += w4.x * v0.y + w4.y * v1.y + w4.z * v2.y + w4.w * v3.y;
        acc.z += w4.x * v0.z + w4.y * v1.z + w4.z * v2.z + w4.w * v3.z;
        acc.w += w4.x * v0.w + w4.y * v1.w + w4.z * v2.w + w4.w * v3.w;
    }
    *(float4*)(g_attn + (size_t)m * 128 + lane * 4) = acc;
}

// ---------------- launch ------------------------------------------------
extern "C" void kernel_launch(void* const* d_in, const int* in_sizes, int n_in,
                              void* d_out, int out_size) {
    const float* low   = (const float*)d_in[0];
    const float* high  = (const float*)d_in[1];
    const float* W1    = (const float*)d_in[2];
    const float* b1    = (const float*)d_in[3];
    const float* W2    = (const float*)d_in[4];
    const float* b2    = (const float*)d_in[5];
    const float* Wq    = (const float*)d_in[6];
    const float* bq    = (const float*)d_in[7];
    const float* Wk    = (const float*)d_in[8];
    const float* bk    = (const float*)d_in[9];
    const float* Wv    = (const float*)d_in[10];
    const float* bv    = (const float*)d_in[11];
    const float* Woff  = (const float*)d_in[12];
    const float* boff  = (const float*)d_in[13];
    const float* Wb    = (const float*)d_in[14];
    const float* gamma = (const float*)d_in[15];
    const float* beta  = (const float*)d_in[16];
    const float* rmean = (const float*)d_in[17];
    const float* rvar  = (const float*)d_in[18];
    float* out = (float*)d_out;

    prep_kernel<<<4160, 256>>>(high, low, Wq, bq, Woff, boff, Wk, bk, Wv, bv);
    gemm_stage1<<<dim3(64, 4), 256>>>(W1, b1, W2, b2);
    gemm_stage2<<<dim3(64, 5), 256>>>();
    attention_kernel<<<MTOT / 8, 256>>>();
    gemm_stage3<<<dim3(64, 4), 256>>>(Wb, gamma, beta, rmean, rvar, out);
}

// round 5
// speedup vs baseline: 2.0608x; 1.5061x over previous
#include <cuda_runtime.h>
#include <cuda_bf16.h>
#include <math.h>
#include <stdint.h>

// ---------------- problem constants ----------------
#define NB   2
#define CH   256
#define INC  128
#define ITC  16
#define NPT  32
#define HL   64
#define WL   64
#define NPIX 4096
#define HH   32
#define WH   32
#define MTOT (NB * NPIX)   // 8192 rows (batch folded into M)

// ---------------- scratch (__device__ globals, no allocs) ----------------
__device__ __align__(16) __nv_bfloat16 g_c1h[MTOT * 512];  // cat1 hi
__device__ __align__(16) __nv_bfloat16 g_c1l[MTOT * 512];  // cat1 lo
__device__ __align__(16) float g_qf  [MTOT * 128];         // NHWC fp32
__device__ __align__(16) float g_vf  [MTOT * 128];         // NHWC fp32
__device__ __align__(16) float g_qoff[MTOT * 80];          // q[16] | off[64]
__device__ __align__(16) float g_kv  [MTOT * 144];         // k[16] | v[128]
__device__ __align__(16) __nv_bfloat16 g_attn_h[MTOT * 128];
__device__ __align__(16) __nv_bfloat16 g_attn_l[MTOT * 128];
__device__ __align__(16) __nv_bfloat16 g_W1h[128 * 512], g_W1l[128 * 512];
__device__ __align__(16) __nv_bfloat16 g_W2h[128 * 256], g_W2l[128 * 256];
__device__ __align__(16) __nv_bfloat16 g_Wbh[256 * 384], g_Wbl[256 * 384];
__device__ __align__(16) float g_Wg1[80 * 128];
__device__ __align__(16) float g_Wg2[144 * 128];
__device__ float g_bg1[80];
__device__ float g_bg2[144];

// ---------------- f32x2 helpers (stage2) ----------------
__device__ __forceinline__ void ffma2(unsigned long long& d, unsigned long long a, unsigned long long b) {
    asm("fma.rn.f32x2 %0, %1, %2, %0;" : "+l"(d) : "l"(a), "l"(b));
}
__device__ __forceinline__ unsigned long long dup2(float x) {
    unsigned long long r;
    asm("mov.b64 %0, {%1, %1};" : "=l"(r) : "f"(x));
    return r;
}
__device__ __forceinline__ float lo32(unsigned long long v) { return __uint_as_float((unsigned)v); }
__device__ __forceinline__ float hi32(unsigned long long v) { return __uint_as_float((unsigned)(v >> 32)); }

// ---------------- mma.sync helpers ----------------
__device__ __forceinline__ uint32_t smem_u32(const void* p) {
    uint32_t a;
    asm("{ .reg .u64 t; cvta.to.shared.u64 t, %1; cvt.u32.u64 %0, t; }" : "=r"(a) : "l"(p));
    return a;
}
__device__ __forceinline__ void ldm_x4(uint32_t* r, uint32_t addr) {
    asm volatile("ldmatrix.sync.aligned.m8n8.x4.shared.b16 {%0,%1,%2,%3}, [%4];"
        : "=r"(r[0]), "=r"(r[1]), "=r"(r[2]), "=r"(r[3]) : "r"(addr));
}
__device__ __forceinline__ void mma_bf16(float* d, const uint32_t* a, const uint32_t* b) {
    asm volatile("mma.sync.aligned.m16n8k16.row.col.f32.bf16.bf16.f32 "
        "{%0,%1,%2,%3}, {%4,%5,%6,%7}, {%8,%9}, {%0,%1,%2,%3};"
        : "+f"(d[0]), "+f"(d[1]), "+f"(d[2]), "+f"(d[3])
        : "r"(a[0]), "r"(a[1]), "r"(a[2]), "r"(a[3]), "r"(b[0]), "r"(b[1]));
}

__device__ __forceinline__ void split_bf16(float x, __nv_bfloat16& h, __nv_bfloat16& l) {
    h = __float2bfloat16(x);
    l = __float2bfloat16(x - __bfloat162float(h));
}

// ---------------- prep: upsample + transpose -> bf16 splits; weight packing --
__global__ void __launch_bounds__(256) prep_kernel(
    const float* __restrict__ high, const float* __restrict__ low,
    const float* __restrict__ W1, const float* __restrict__ W2,
    const float* __restrict__ Wb,
    const float* __restrict__ Wq, const float* __restrict__ bq,
    const float* __restrict__ Woff, const float* __restrict__ boff,
    const float* __restrict__ Wk, const float* __restrict__ bk,
    const float* __restrict__ Wv, const float* __restrict__ bv)
{
    int blk = blockIdx.x;
    int tid = threadIdx.x;

    if (blk >= 4096) {
        for (int e = (blk - 4096) * 256 + tid; e < 225504; e += 16384) {
            if (e < 65536) {
                split_bf16(W1[e], g_W1h[e], g_W1l[e]);
            } else if (e < 98304) {
                int t = e - 65536;
                split_bf16(W2[t], g_W2h[t], g_W2l[t]);
            } else if (e < 196608) {
                int t = e - 98304;
                split_bf16(Wb[t], g_Wbh[t], g_Wbl[t]);
            } else if (e < 206848) {
                int t = e - 196608;
                int r = t >> 7, k = t & 127;
                g_Wg1[t] = (r < 16) ? Wq[r * 128 + k] : Woff[(r - 16) * 128 + k];
            } else if (e < 225280) {
                int t = e - 206848;
                int r = t >> 7, k = t & 127;
                g_Wg2[t] = (r < 16) ? Wk[r * 128 + k] : Wv[(r - 16) * 128 + k];
            } else if (e < 225360) {
                int i = e - 225280;
                g_bg1[i] = (i < 16) ? bq[i] : boff[i - 16];
            } else {
                int i = e - 225360;
                g_bg2[i] = (i < 16) ? bk[i] : bv[i - 16];
            }
        }
        return;
    }

    int part = blk >> 11;          // 0: high_up, 1: low
    int r = blk & 2047;
    int b = r >> 10;
    int r2 = r & 1023;
    int pt = r2 >> 3;
    int ct = r2 & 7;
    int p0 = pt * 32;
    int c0 = ct * 32;

    __shared__ float s[32][33];
    int px = tid & 31;
    int cq = tid >> 5;

    if (part == 1) {
        #pragma unroll
        for (int i = 0; i < 4; i++) {
            int c = cq * 4 + i;
            s[c][px] = low[((size_t)(b * CH + c0 + c)) * NPIX + p0 + px];
        }
    } else {
        int y = p0 >> 6;
        int xb = p0 & 63;
        float fy = y * 0.5f - 0.25f;
        float y0f = floorf(fy);
        float wy = fy - y0f;
        int iy0 = min(max((int)y0f, 0), HH - 1);
        int iy1 = min(max((int)y0f + 1, 0), HH - 1);
        int x = xb + px;
        float fx = x * 0.5f - 0.25f;
        float x0f = floorf(fx);
        float wx = fx - x0f;
        int ix0 = min(max((int)x0f, 0), WH - 1);
        int ix1 = min(max((int)x0f + 1, 0), WH - 1);
        #pragma unroll
        for (int i = 0; i < 4; i++) {
            int c = cq * 4 + i;
            const float* src = high + ((size_t)(b * CH + c0 + c)) * (HH * WH);
            float v00 = src[iy0 * WH + ix0], v01 = src[iy0 * WH + ix1];
            float v10 = src[iy1 * WH + ix0], v11 = src[iy1 * WH + ix1];
            s[c][px] = (1.f - wx) * (1.f - wy) * v00 + wx * (1.f - wy) * v01
                     + (1.f - wx) * wy * v10 + wx * wy * v11;
        }
    }
    __syncthreads();

    int cc = tid & 31;
    int pq = tid >> 5;
    int base_c = (part == 0 ? c0 : 256 + c0) + cc;
    #pragma unroll
    for (int i = 0; i < 4; i++) {
        int pp = pq * 4 + i;
        size_t idx = ((size_t)(b * NPIX + p0 + pp)) * 512 + base_c;
        __nv_bfloat16 h, l;
        split_bf16(s[cc][pp], h, l);
        g_c1h[idx] = h;
        g_c1l[idx] = l;
    }
}

// ---------------- bf16x3 mma.sync GEMM (stage1 & stage3) -----------------
// Block 128(M) x 128(N), 8 warps (2x4), warp tile 64x32, K-chunk 32,
// double-buffered smem, pitch 40 bf16 (conflict-free ldmatrix phases).
#define PITCH 40
#define TILE_ELEMS (128 * PITCH)

__global__ void __launch_bounds__(256) hmma_kernel(
    int stage,
    const float* __restrict__ bias0, const float* __restrict__ bias1,
    const float* __restrict__ gamma, const float* __restrict__ beta,
    const float* __restrict__ rmean, const float* __restrict__ rvar,
    float* __restrict__ out)
{
    extern __shared__ __nv_bfloat16 sm[];
    int tid = threadIdx.x;
    int wid = tid >> 5, lane = tid & 31;
    int wm = wid >> 2, wn = wid & 3;
    int gid = lane >> 2, tg = lane & 3;
    int m0 = blockIdx.x * 128;
    int by = blockIdx.y;

    int K, ldb;
    const __nv_bfloat16 *Bh, *Bl;
    float* Yf = nullptr;
    const float* bias = nullptr;
    if (stage == 0) {
        if (by == 0) { K = 512; Bh = g_W1h; Bl = g_W1l; ldb = 512; Yf = g_qf; bias = bias0; }
        else         { K = 256; Bh = g_W2h; Bl = g_W2l; ldb = 256; Yf = g_vf; bias = bias1; }
    } else {
        K = 384; ldb = 384;
        Bh = g_Wbh + (size_t)by * 128 * 384;
        Bl = g_Wbl + (size_t)by * 128 * 384;
    }
    int nc = K >> 5;

    float d[4][4][4];
    #pragma unroll
    for (int i = 0; i < 4; i++)
        #pragma unroll
        for (int j = 0; j < 4; j++)
            #pragma unroll
            for (int k = 0; k < 4; k++) d[i][j][k] = 0.f;

    int seg = tid & 3;           // 16B segment within 64B k-chunk row
    int r0 = tid >> 2;           // rows r0, r0+64

    uint4 stg[8];
    auto ldg_chunk = [&](int c) {
        const __nv_bfloat16 *Ah_src, *Al_src;
        int lda, colA;
        if (stage == 0)   { Ah_src = g_c1h; Al_src = g_c1l; lda = 512; colA = c * 32; }
        else if (c < 4)   { Ah_src = g_attn_h; Al_src = g_attn_l; lda = 128; colA = c * 32; }
        else              { Ah_src = g_c1h; Al_src = g_c1l; lda = 512; colA = (c - 4) * 32; }
        const __nv_bfloat16* ah = Ah_src + (size_t)m0 * lda + colA + seg * 8;
        const __nv_bfloat16* al = Al_src + (size_t)m0 * lda + colA + seg * 8;
        const __nv_bfloat16* bh = Bh + c * 32 + seg * 8;
        const __nv_bfloat16* bl = Bl + c * 32 + seg * 8;
        stg[0] = *(const uint4*)(ah + (size_t)r0 * lda);
        stg[1] = *(const uint4*)(ah + (size_t)(r0 + 64) * lda);
        stg[2] = *(const uint4*)(al + (size_t)r0 * lda);
        stg[3] = *(const uint4*)(al + (size_t)(r0 + 64) * lda);
        stg[4] = *(const uint4*)(bh + (size_t)r0 * ldb);
        stg[5] = *(const uint4*)(bh + (size_t)(r0 + 64) * ldb);
        stg[6] = *(const uint4*)(bl + (size_t)r0 * ldb);
        stg[7] = *(const uint4*)(bl + (size_t)(r0 + 64) * ldb);
    };
    auto sts_chunk = [&](int buf) {
        #pragma unroll
        for (int t = 0; t < 4; t++) {
            __nv_bfloat16* base = sm + (buf * 4 + t) * TILE_ELEMS;
            *(uint4*)(base + r0 * PITCH + seg * 8)         = stg[t * 2];
            *(uint4*)(base + (r0 + 64) * PITCH + seg * 8)  = stg[t * 2 + 1];
        }
    };

    uint32_t sm0 = smem_u32(sm);
    auto compute = [&](int buf) {
        uint32_t aAh = sm0 + (buf * 4 + 0) * TILE_ELEMS * 2;
        uint32_t aAl = sm0 + (buf * 4 + 1) * TILE_ELEMS * 2;
        uint32_t aBh = sm0 + (buf * 4 + 2) * TILE_ELEMS * 2;
        uint32_t aBl = sm0 + (buf * 4 + 3) * TILE_ELEMS * 2;
        #pragma unroll
        for (int h = 0; h < 2; h++) {
            uint32_t ah[4][4], al[4][4], bh[2][4], bl[2][4];
            uint32_t a_off = (uint32_t)((wm * 64 + (lane & 15)) * (PITCH * 2)
                                        + h * 32 + (lane >> 4) * 16);
            #pragma unroll
            for (int mt = 0; mt < 4; mt++) {
                ldm_x4(ah[mt], aAh + a_off + mt * 16 * (PITCH * 2));
                ldm_x4(al[mt], aAl + a_off + mt * 16 * (PITCH * 2));
            }
            int q = lane >> 3;
            uint32_t b_off = (uint32_t)((wn * 32 + (q >> 1) * 8 + (lane & 7)) * (PITCH * 2)
                                        + h * 32 + (q & 1) * 16);
            ldm_x4(bh[0], aBh + b_off);
            ldm_x4(bh[1], aBh + b_off + 16 * (PITCH * 2));
            ldm_x4(bl[0], aBl + b_off);
            ldm_x4(bl[1], aBl + b_off + 16 * (PITCH * 2));
            #pragma unroll
            for (int mt = 0; mt < 4; mt++) {
                #pragma unroll
                for (int nt = 0; nt < 4; nt++) {
                    const uint32_t* pbh = &bh[nt >> 1][(nt & 1) * 2];
                    const uint32_t* pbl = &bl[nt >> 1][(nt & 1) * 2];
                    mma_bf16(d[mt][nt], ah[mt], pbh);
                    mma_bf16(d[mt][nt], ah[mt], pbl);
                    mma_bf16(d[mt][nt], al[mt], pbh);
                }
            }
        }
    };

    ldg_chunk(0);
    sts_chunk(0);
    __syncthreads();
    for (int c = 0; c < nc; c++) {
        if (c + 1 < nc) ldg_chunk(c + 1);
        compute(c & 1);
        if (c + 1 < nc) sts_chunk((c + 1) & 1);
        __syncthreads();
    }

    if (stage == 0) {
        #pragma unroll
        for (int mt = 0; mt < 4; mt++) {
            int m = m0 + wm * 64 + mt * 16 + gid;
            #pragma unroll
            for (int nt = 0; nt < 4; nt++) {
                int cc = wn * 32 + nt * 8 + tg * 2;
                float bx = bias[cc], byv = bias[cc + 1];
                float2 lo = make_float2(d[mt][nt][0] + bx, d[mt][nt][1] + byv);
                float2 hi = make_float2(d[mt][nt][2] + bx, d[mt][nt][3] + byv);
                *(float2*)(Yf + (size_t)m * 128 + cc) = lo;
                *(float2*)(Yf + (size_t)(m + 8) * 128 + cc) = hi;
            }
        }
    } else {
        int bidx = m0 >> 12;
        int pixbase = (m0 & 4095) + wm * 64;
        #pragma unroll
        for (int nt = 0; nt < 4; nt++) {
            int oc = by * 128 + wn * 32 + nt * 8 + tg * 2;
            float inv0 = rsqrtf(rvar[oc] + 1e-5f);
            float sc0 = gamma[oc] * inv0;
            float sh0 = beta[oc] - rmean[oc] * sc0;
            float inv1 = rsqrtf(rvar[oc + 1] + 1e-5f);
            float sc1 = gamma[oc + 1] * inv1;
            float sh1 = beta[oc + 1] - rmean[oc + 1] * sc1;
            float* o0 = out + ((size_t)(bidx * 256 + oc)) * NPIX;
            float* o1 = out + ((size_t)(bidx * 256 + oc + 1)) * NPIX;
            #pragma unroll
            for (int mt = 0; mt < 4; mt++) {
                int pix = pixbase + mt * 16 + gid;
                o0[pix]     = fmaxf(d[mt][nt][0] * sc0 + sh0, 0.f);
                o1[pix]     = fmaxf(d[mt][nt][1] * sc1 + sh1, 0.f);
                o0[pix + 8] = fmaxf(d[mt][nt][2] * sc0 + sh0, 0.f);
                o1[pix + 8] = fmaxf(d[mt][nt][3] * sc1 + sh1, 0.f);
            }
        }
    }
}

// ---------------- f32x2 GEMM (stage2 only) ------------------------------
#define TM 128
#define TN 64
#define BK 16

__device__ __forceinline__ void gemm_core(
    float* As, float* Bs,
    const float* __restrict__ W, const float* __restrict__ bias,
    int O, int K,
    const float* __restrict__ X0, int ld0,
    float* __restrict__ Y, int ldy,
    int m0, int n0)
{
    int tid = threadIdx.x;
    int mrow = tid & 127, khalf = tid >> 7;
    int nrow = tid & 63,  kq = tid >> 6;

    const float* xrow0 = X0 + (size_t)(m0 + mrow) * ld0;
    int o_load = n0 + nrow;
    bool ovalid = (o_load < O);
    const float* wrow = W + (size_t)(ovalid ? o_load : 0) * K;

    float4 ra0, ra1, rb;
    auto LDG = [&](int k0) {
        int k = k0 + khalf * 8;
        ra0 = *(const float4*)&xrow0[k];
        ra1 = *(const float4*)&xrow0[k + 4];
        rb = ovalid ? *(const float4*)&wrow[k0 + kq * 4] : make_float4(0.f, 0.f, 0.f, 0.f);
    };
    auto STS = [&](int buf) {
        float* ab = As + buf * (BK * TM);
        int kb = khalf * 8;
        ab[(kb + 0) * TM + mrow] = ra0.x;
        ab[(kb + 1) * TM + mrow] = ra0.y;
        ab[(kb + 2) * TM + mrow] = ra0.z;
        ab[(kb + 3) * TM + mrow] = ra0.w;
        ab[(kb + 4) * TM + mrow] = ra1.x;
        ab[(kb + 5) * TM + mrow] = ra1.y;
        ab[(kb + 6) * TM + mrow] = ra1.z;
        ab[(kb + 7) * TM + mrow] = ra1.w;
        float* bbuf = Bs + buf * (BK * TN);
        bbuf[(kq * 4 + 0) * TN + nrow] = rb.x;
        bbuf[(kq * 4 + 1) * TN + nrow] = rb.y;
        bbuf[(kq * 4 + 2) * TN + nrow] = rb.z;
        bbuf[(kq * 4 + 3) * TN + nrow] = rb.w;
    };

    int tx = tid & 15, ty = tid >> 4;
    unsigned long long acc[4][4];
    #pragma unroll
    for (int i = 0; i < 4; i++)
        #pragma unroll
        for (int j = 0; j < 4; j++) acc[i][j] = 0ULL;

    int nk = K / BK;
    LDG(0);
    STS(0);
    __syncthreads();

    for (int t = 0; t < nk; t++) {
        if (t + 1 < nk) LDG((t + 1) * BK);
        int buf = t & 1;
        const float* ab = As + buf * (BK * TM);
        const float* bbuf = Bs + buf * (BK * TN);
        #pragma unroll
        for (int kk = 0; kk < BK; kk++) {
            const unsigned long long* Ap =
                (const unsigned long long*)(ab + kk * TM + ty * 8);
            unsigned long long a0 = Ap[0], a1 = Ap[1], a2 = Ap[2], a3 = Ap[3];
            const float* bp = bbuf + kk * TN + tx * 4;
            unsigned long long b0 = dup2(bp[0]);
            unsigned long long b1 = dup2(bp[1]);
            unsigned long long b2 = dup2(bp[2]);
            unsigned long long b3 = dup2(bp[3]);
            ffma2(acc[0][0], a0, b0); ffma2(acc[0][1], a0, b1);
            ffma2(acc[0][2], a0, b2); ffma2(acc[0][3], a0, b3);
            ffma2(acc[1][0], a1, b0); ffma2(acc[1][1], a1, b1);
            ffma2(acc[1][2], a1, b2); ffma2(acc[1][3], a1, b3);
            ffma2(acc[2][0], a2, b0); ffma2(acc[2][1], a2, b1);
            ffma2(acc[2][2], a2, b2); ffma2(acc[2][3], a2, b3);
            ffma2(acc[3][0], a3, b0); ffma2(acc[3][1], a3, b1);
            ffma2(acc[3][2], a3, b2); ffma2(acc[3][3], a3, b3);
        }
        if (t + 1 < nk) {
            STS(buf ^ 1);
            __syncthreads();
        }
    }

    int oc = n0 + tx * 4;
    if (oc < O) {
        float bx = bias[oc + 0], by2 = bias[oc + 1], bz = bias[oc + 2], bw = bias[oc + 3];
        #pragma unroll
        for (int i = 0; i < 4; i++) {
            int m = m0 + ty * 8 + i * 2;
            float4 r0, r1;
            r0.x = lo32(acc[i][0]) + bx; r0.y = lo32(acc[i][1]) + by2;
            r0.z = lo32(acc[i][2]) + bz; r0.w = lo32(acc[i][3]) + bw;
            r1.x = hi32(acc[i][0]) + bx; r1.y = hi32(acc[i][1]) + by2;
            r1.z = hi32(acc[i][2]) + bz; r1.w = hi32(acc[i][3]) + bw;
            *(float4*)&Y[(size_t)m * ldy + oc] = r0;
            *(float4*)&Y[(size_t)(m + 1) * ldy + oc] = r1;
        }
    }
}

__global__ void __launch_bounds__(256) gemm_stage2()
{
    __shared__ float As[2 * BK * TM];
    __shared__ float Bs[2 * BK * TN];
    int m0 = blockIdx.x * TM;
    int by = blockIdx.y;
    if (by < 2)
        gemm_core(As, Bs, g_Wg1, g_bg1, 80, 128, g_qf, 128, g_qoff, 80, m0, by * 64);
    else
        gemm_core(As, Bs, g_Wg2, g_bg2, 144, 128, g_vf, 128, g_kv, 144, m0, (by - 2) * 64);
}

// ---------------- deformable point attention ----------------------------
__global__ void __launch_bounds__(256) attention_kernel()
{
    __shared__ int   sIdx[8][128];
    __shared__ float sW  [8][128];
    __shared__ float sAttn[8][32];
    int warp = threadIdx.x >> 5;
    int lane = threadIdx.x & 31;
    int m = blockIdx.x * 8 + warp;
    int b = m >> 12;
    int n = m & (NPIX - 1);

    const float* row = g_qoff + (size_t)m * 80;

    float2 d = *(const float2*)(row + 16 + 2 * lane);
    float sx = (float)(n & 63) + d.x;
    float sy = (float)(n >> 6) + d.y;
    float x0f = floorf(sx), y0f = floorf(sy);
    float wx = sx - x0f,    wy = sy - y0f;
    int ix0 = min(max((int)x0f, 0), WL - 1);
    int ix1 = min(max((int)x0f + 1, 0), WL - 1);
    int iy0 = min(max((int)y0f, 0), HL - 1);
    int iy1 = min(max((int)y0f + 1, 0), HL - 1);
    int g00 = (iy0 * WL + ix0) * 36, g01 = (iy0 * WL + ix1) * 36;
    int g10 = (iy1 * WL + ix0) * 36, g11 = (iy1 * WL + ix1) * 36;
    float w00 = (1.f - wx) * (1.f - wy), w01 = wx * (1.f - wy);
    float w10 = (1.f - wx) * wy,         w11 = wx * wy;

    int cq = lane & 3;
    int oct = lane >> 2;
    float4 qv = *(const float4*)(row + 4 * cq);
    const float4* kvb = (const float4*)(g_kv + (size_t)b * NPIX * 144);

    float logit[4];
    #pragma unroll
    for (int g = 0; g < 4; g++) {
        int src = oct + 8 * g;
        int G0 = __shfl_sync(0xffffffffu, g00, src);
        int G1 = __shfl_sync(0xffffffffu, g01, src);
        int G2 = __shfl_sync(0xffffffffu, g10, src);
        int G3 = __shfl_sync(0xffffffffu, g11, src);
        float W0 = __shfl_sync(0xffffffffu, w00, src);
        float W1 = __shfl_sync(0xffffffffu, w01, src);
        float W2 = __shfl_sync(0xffffffffu, w10, src);
        float W3 = __shfl_sync(0xffffffffu, w11, src);
        float4 k0 = kvb[G0 + cq];
        float4 k1 = kvb[G1 + cq];
        float4 k2 = kvb[G2 + cq];
        float4 k3 = kvb[G3 + cq];
        float ksx = W0 * k0.x + W1 * k1.x + W2 * k2.x + W3 * k3.x;
        float ksy = W0 * k0.y + W1 * k1.y + W2 * k2.y + W3 * k3.y;
        float ksz = W0 * k0.z + W1 * k1.z + W2 * k2.z + W3 * k3.z;
        float ksw = W0 * k0.w + W1 * k1.w + W2 * k2.w + W3 * k3.w;
        float part = qv.x * ksx + qv.y * ksy + qv.z * ksz + qv.w * ksw;
        part += __shfl_xor_sync(0xffffffffu, part, 1);
        part += __shfl_xor_sync(0xffffffffu, part, 2);
        logit[g] = part * 0.25f;
        int   Gq = (cq == 0) ? G0 : (cq == 1) ? G1 : (cq == 2) ? G2 : G3;
        float Wq = (cq == 0) ? W0 : (cq == 1) ? W1 : (cq == 2) ? W2 : W3;
        sIdx[warp][src * 4 + cq] = Gq;
        sW  [warp][src * 4 + cq] = Wq;
    }

    float mx = fmaxf(fmaxf(logit[0], logit[1]), fmaxf(logit[2], logit[3]));
    mx = fmaxf(mx, __shfl_xor_sync(0xffffffffu, mx, 4));
    mx = fmaxf(mx, __shfl_xor_sync(0xffffffffu, mx, 8));
    mx = fmaxf(mx, __shfl_xor_sync(0xffffffffu, mx, 16));
    float e0 = expf(logit[0] - mx), e1 = expf(logit[1] - mx);
    float e2 = expf(logit[2] - mx), e3 = expf(logit[3] - mx);
    float sum = e0 + e1 + e2 + e3;
    sum += __shfl_xor_sync(0xffffffffu, sum, 4);
    sum += __shfl_xor_sync(0xffffffffu, sum, 8);
    sum += __shfl_xor_sync(0xffffffffu, sum, 16);
    float inv = 1.f / sum;
    if (cq == 0) {
        sAttn[warp][oct + 0]  = e0 * inv;
        sAttn[warp][oct + 8]  = e1 * inv;
        sAttn[warp][oct + 16] = e2 * inv;
        sAttn[warp][oct + 24] = e3 * inv;
    }
    __syncwarp();

    {
        float a = sAttn[warp][lane];
        float4 w4 = *(float4*)&sW[warp][lane * 4];
        w4.x *= a; w4.y *= a; w4.z *= a; w4.w *= a;
        *(float4*)&sW[warp][lane * 4] = w4;
    }
    __syncwarp();

    float4 acc = make_float4(0.f, 0.f, 0.f, 0.f);
    #pragma unroll 2
    for (int t = 0; t < 128; t += 4) {
        int4   i4 = *(const int4*)&sIdx[warp][t];
        float4 w4 = *(const float4*)&sW[warp][t];
        float4 v0 = kvb[i4.x + 4 + lane];
        float4 v1 = kvb[i4.y + 4 + lane];
        float4 v2 = kvb[i4.z + 4 + lane];
        float4 v3 = kvb[i4.w + 4 + lane];
        acc.x += w4.x * v0.x + w4.y * v1.x + w4.z * v2.x + w4.w * v3.x;
        acc.y += w4.x * v0.y + w4.y * v1.y + w4.z * v2.y + w4.w * v3.y;
        acc.z += w4.x * v0.z + w4.y * v1.z + w4.z * v2.z + w4.w * v3.z;
        acc.w += w4.x * v0.w + w4.y * v1.w + w4.z * v2.w + w4.w * v3.w;
    }
    size_t base = (size_t)m * 128 + lane * 4;
    __nv_bfloat16 hv[4], lv[4];
    split_bf16(acc.x, hv[0], lv[0]);
    split_bf16(acc.y, hv[1], lv[1]);
    split_bf16(acc.z, hv[2], lv[2]);
    split_bf16(acc.w, hv[3], lv[3]);
    *(uint2*)&g_attn_h[base] = *(uint2*)hv;
    *(uint2*)&g_attn_l[base] = *(uint2*)lv;
}

// ---------------- launch ------------------------------------------------
extern "C" void kernel_launch(void* const* d_in, const int* in_sizes, int n_in,
                              void* d_out, int out_size) {
    const float* low   = (const float*)d_in[0];
    const float* high  = (const float*)d_in[1];
    const float* W1    = (const float*)d_in[2];
    const float* b1    = (const float*)d_in[3];
    const float* W2    = (const float*)d_in[4];
    const float* b2    = (const float*)d_in[5];
    const float* Wq    = (const float*)d_in[6];
    const float* bq    = (const float*)d_in[7];
    const float* Wk    = (const float*)d_in[8];
    const float* bk    = (const float*)d_in[9];
    const float* Wv    = (const float*)d_in[10];
    const float* bv    = (const float*)d_in[11];
    const float* Woff  = (const float*)d_in[12];
    const float* boff  = (const float*)d_in[13];
    const float* Wb    = (const float*)d_in[14];
    const float* gamma = (const float*)d_in[15];
    const float* beta  = (const float*)d_in[16];
    const float* rmean = (const float*)d_in[17];
    const float* rvar  = (const float*)d_in[18];
    float* out = (float*)d_out;

    const int HMMA_SMEM = 2 * 4 * TILE_ELEMS * 2;  // 81920 bytes
    cudaFuncSetAttribute(hmma_kernel, cudaFuncAttributeMaxDynamicSharedMemorySize, HMMA_SMEM);

    prep_kernel<<<4160, 256>>>(high, low, W1, W2, Wb,
                               Wq, bq, Woff, boff, Wk, bk, Wv, bv);
    hmma_kernel<<<dim3(64, 2), 256, HMMA_SMEM>>>(
        0, b1, b2, nullptr, nullptr, nullptr, nullptr, nullptr);
    gemm_stage2<<<dim3(64, 5), 256>>>();
    attention_kernel<<<MTOT / 8, 256>>>();
    hmma_kernel<<<dim3(64, 2), 256, HMMA_SMEM>>>(
        1, nullptr, nullptr, gamma, beta, rmean, rvar, out);
}

// round 6
// speedup vs baseline: 2.3425x; 1.1367x over previous
#include <cuda_runtime.h>
#include <cuda_bf16.h>
#include <math.h>
#include <stdint.h>

// ---------------- problem constants ----------------
#define NB   2
#define CH   256
#define INC  128
#define ITC  16
#define NPT  32
#define HL   64
#define WL   64
#define NPIX 4096
#define HH   32
#define WH   32
#define MTOT (NB * NPIX)   // 8192 rows (batch folded into M)

// ---------------- scratch (__device__ globals, no allocs) ----------------
__device__ __align__(16) __nv_bfloat16 g_c1h[MTOT * 512];  // cat1 hi
__device__ __align__(16) __nv_bfloat16 g_c1l[MTOT * 512];  // cat1 lo
__device__ __align__(16) __nv_bfloat16 g_fh [MTOT * 256];  // qf|vf hi
__device__ __align__(16) __nv_bfloat16 g_fl [MTOT * 256];  // qf|vf lo
__device__ __align__(16) float g_qoff[MTOT * 80];          // q[16] | off[64]
__device__ __align__(16) float g_kv  [MTOT * 144];         // k[16] | v[128]
__device__ __align__(16) __nv_bfloat16 g_attn_h[MTOT * 128];
__device__ __align__(16) __nv_bfloat16 g_attn_l[MTOT * 128];
__device__ __align__(16) __nv_bfloat16 g_W1h[128 * 512], g_W1l[128 * 512];
__device__ __align__(16) __nv_bfloat16 g_W2h[128 * 256], g_W2l[128 * 256];
__device__ __align__(16) __nv_bfloat16 g_Wbh[256 * 384], g_Wbl[256 * 384];
__device__ __align__(16) __nv_bfloat16 g_Wgh[256 * 256], g_Wgl[256 * 256];  // block-diag [q;off;k;v], rows 224-255 zero
__device__ float g_bg[256];

// ---------------- mma.sync helpers ----------------
__device__ __forceinline__ uint32_t smem_u32(const void* p) {
    uint32_t a;
    asm("{ .reg .u64 t; cvta.to.shared.u64 t, %1; cvt.u32.u64 %0, t; }" : "=r"(a) : "l"(p));
    return a;
}
__device__ __forceinline__ void ldm_x4(uint32_t* r, uint32_t addr) {
    asm volatile("ldmatrix.sync.aligned.m8n8.x4.shared.b16 {%0,%1,%2,%3}, [%4];"
        : "=r"(r[0]), "=r"(r[1]), "=r"(r[2]), "=r"(r[3]) : "r"(addr));
}
__device__ __forceinline__ void mma_bf16(float* d, const uint32_t* a, const uint32_t* b) {
    asm volatile("mma.sync.aligned.m16n8k16.row.col.f32.bf16.bf16.f32 "
        "{%0,%1,%2,%3}, {%4,%5,%6,%7}, {%8,%9}, {%0,%1,%2,%3};"
        : "+f"(d[0]), "+f"(d[1]), "+f"(d[2]), "+f"(d[3])
        : "r"(a[0]), "r"(a[1]), "r"(a[2]), "r"(a[3]), "r"(b[0]), "r"(b[1]));
}

__device__ __forceinline__ void split_bf16(float x, __nv_bfloat16& h, __nv_bfloat16& l) {
    h = __float2bfloat16(x);
    l = __float2bfloat16(x - __bfloat162float(h));
}

// ---------------- prep: upsample + transpose -> bf16 splits; weight packing --
__global__ void __launch_bounds__(256) prep_kernel(
    const float* __restrict__ high, const float* __restrict__ low,
    const float* __restrict__ W1, const float* __restrict__ W2,
    const float* __restrict__ Wb,
    const float* __restrict__ Wq, const float* __restrict__ bq,
    const float* __restrict__ Woff, const float* __restrict__ boff,
    const float* __restrict__ Wk, const float* __restrict__ bk,
    const float* __restrict__ Wv, const float* __restrict__ bv)
{
    int blk = blockIdx.x;
    int tid = threadIdx.x;

    if (blk >= 4096) {
        for (int e = (blk - 4096) * 256 + tid; e < 262400; e += 16384) {
            if (e < 65536) {
                split_bf16(W1[e], g_W1h[e], g_W1l[e]);
            } else if (e < 98304) {
                int t = e - 65536;
                split_bf16(W2[t], g_W2h[t], g_W2l[t]);
            } else if (e < 196608) {
                int t = e - 98304;
                split_bf16(Wb[t], g_Wbh[t], g_Wbl[t]);
            } else if (e < 262144) {
                // block-diagonal packed stage2 weight [256 out][256 in]
                int t = e - 196608;
                int r = t >> 8, k = t & 255;
                float v = 0.f;
                if (r < 16)       { if (k < 128)  v = Wq[r * 128 + k]; }
                else if (r < 80)  { if (k < 128)  v = Woff[(r - 16) * 128 + k]; }
                else if (r < 96)  { if (k >= 128) v = Wk[(r - 80) * 128 + k - 128]; }
                else if (r < 224) { if (k >= 128) v = Wv[(r - 96) * 128 + k - 128]; }
                split_bf16(v, g_Wgh[t], g_Wgl[t]);
            } else {
                int i = e - 262144;
                float v = 0.f;
                if (i < 16)       v = bq[i];
                else if (i < 80)  v = boff[i - 16];
                else if (i < 96)  v = bk[i - 80];
                else if (i < 224) v = bv[i - 96];
                g_bg[i] = v;
            }
        }
        return;
    }

    int part = blk >> 11;          // 0: high_up, 1: low
    int r = blk & 2047;
    int b = r >> 10;
    int r2 = r & 1023;
    int pt = r2 >> 3;
    int ct = r2 & 7;
    int p0 = pt * 32;
    int c0 = ct * 32;

    __shared__ float s[32][33];
    int px = tid & 31;
    int cq = tid >> 5;

    if (part == 1) {
        #pragma unroll
        for (int i = 0; i < 4; i++) {
            int c = cq * 4 + i;
            s[c][px] = low[((size_t)(b * CH + c0 + c)) * NPIX + p0 + px];
        }
    } else {
        int y = p0 >> 6;
        int xb = p0 & 63;
        float fy = y * 0.5f - 0.25f;
        float y0f = floorf(fy);
        float wy = fy - y0f;
        int iy0 = min(max((int)y0f, 0), HH - 1);
        int iy1 = min(max((int)y0f + 1, 0), HH - 1);
        int x = xb + px;
        float fx = x * 0.5f - 0.25f;
        float x0f = floorf(fx);
        float wx = fx - x0f;
        int ix0 = min(max((int)x0f, 0), WH - 1);
        int ix1 = min(max((int)x0f + 1, 0), WH - 1);
        #pragma unroll
        for (int i = 0; i < 4; i++) {
            int c = cq * 4 + i;
            const float* src = high + ((size_t)(b * CH + c0 + c)) * (HH * WH);
            float v00 = src[iy0 * WH + ix0], v01 = src[iy0 * WH + ix1];
            float v10 = src[iy1 * WH + ix0], v11 = src[iy1 * WH + ix1];
            s[c][px] = (1.f - wx) * (1.f - wy) * v00 + wx * (1.f - wy) * v01
                     + (1.f - wx) * wy * v10 + wx * wy * v11;
        }
    }
    __syncthreads();

    int cc = tid & 31;
    int pq = tid >> 5;
    int base_c = (part == 0 ? c0 : 256 + c0) + cc;
    #pragma unroll
    for (int i = 0; i < 4; i++) {
        int pp = pq * 4 + i;
        size_t idx = ((size_t)(b * NPIX + p0 + pp)) * 512 + base_c;
        __nv_bfloat16 h, l;
        split_bf16(s[cc][pp], h, l);
        g_c1h[idx] = h;
        g_c1l[idx] = l;
    }
}

// ---------------- bf16x3 mma.sync GEMM (stages 0,1,2) --------------------
// Block 128(M) x 128(N), 8 warps (2x4), warp tile 64x32, K-chunk 32,
// double-buffered smem, pitch 40 bf16.
#define PITCH 40
#define TILE_ELEMS (128 * PITCH)

__global__ void __launch_bounds__(256) hmma_kernel(
    int stage,
    const float* __restrict__ bias0, const float* __restrict__ bias1,
    const float* __restrict__ gamma, const float* __restrict__ beta,
    const float* __restrict__ rmean, const float* __restrict__ rvar,
    float* __restrict__ out)
{
    extern __shared__ __nv_bfloat16 sm[];
    int tid = threadIdx.x;
    int wid = tid >> 5, lane = tid & 31;
    int wm = wid >> 2, wn = wid & 3;
    int gid = lane >> 2, tg = lane & 3;
    int m0 = blockIdx.x * 128;
    int by = blockIdx.y;

    int K, ldb;
    const __nv_bfloat16 *Bh, *Bl;
    const float* bias = nullptr;
    if (stage == 0) {
        if (by == 0) { K = 512; Bh = g_W1h; Bl = g_W1l; ldb = 512; bias = bias0; }
        else         { K = 256; Bh = g_W2h; Bl = g_W2l; ldb = 256; bias = bias1; }
    } else if (stage == 1) {
        K = 256; ldb = 256;
        Bh = g_Wgh + (size_t)by * 128 * 256;
        Bl = g_Wgl + (size_t)by * 128 * 256;
    } else {
        K = 384; ldb = 384;
        Bh = g_Wbh + (size_t)by * 128 * 384;
        Bl = g_Wbl + (size_t)by * 128 * 384;
    }
    int nc = K >> 5;

    float d[4][4][4];
    #pragma unroll
    for (int i = 0; i < 4; i++)
        #pragma unroll
        for (int j = 0; j < 4; j++)
            #pragma unroll
            for (int k = 0; k < 4; k++) d[i][j][k] = 0.f;

    int seg = tid & 3;
    int r0 = tid >> 2;

    uint4 stg[8];
    auto ldg_chunk = [&](int c) {
        const __nv_bfloat16 *Ah_src, *Al_src;
        int lda, colA;
        if (stage == 0)      { Ah_src = g_c1h; Al_src = g_c1l; lda = 512; colA = c * 32; }
        else if (stage == 1) { Ah_src = g_fh;  Al_src = g_fl;  lda = 256; colA = c * 32; }
        else if (c < 4)      { Ah_src = g_attn_h; Al_src = g_attn_l; lda = 128; colA = c * 32; }
        else                 { Ah_src = g_c1h; Al_src = g_c1l; lda = 512; colA = (c - 4) * 32; }
        const __nv_bfloat16* ah = Ah_src + (size_t)m0 * lda + colA + seg * 8;
        const __nv_bfloat16* al = Al_src + (size_t)m0 * lda + colA + seg * 8;
        const __nv_bfloat16* bh = Bh + c * 32 + seg * 8;
        const __nv_bfloat16* bl = Bl + c * 32 + seg * 8;
        stg[0] = *(const uint4*)(ah + (size_t)r0 * lda);
        stg[1] = *(const uint4*)(ah + (size_t)(r0 + 64) * lda);
        stg[2] = *(const uint4*)(al + (size_t)r0 * lda);
        stg[3] = *(const uint4*)(al + (size_t)(r0 + 64) * lda);
        stg[4] = *(const uint4*)(bh + (size_t)r0 * ldb);
        stg[5] = *(const uint4*)(bh + (size_t)(r0 + 64) * ldb);
        stg[6] = *(const uint4*)(bl + (size_t)r0 * ldb);
        stg[7] = *(const uint4*)(bl + (size_t)(r0 + 64) * ldb);
    };
    auto sts_chunk = [&](int buf) {
        #pragma unroll
        for (int t = 0; t < 4; t++) {
            __nv_bfloat16* base = sm + (buf * 4 + t) * TILE_ELEMS;
            *(uint4*)(base + r0 * PITCH + seg * 8)         = stg[t * 2];
            *(uint4*)(base + (r0 + 64) * PITCH + seg * 8)  = stg[t * 2 + 1];
        }
    };

    uint32_t sm0 = smem_u32(sm);
    auto compute = [&](int buf) {
        uint32_t aAh = sm0 + (buf * 4 + 0) * TILE_ELEMS * 2;
        uint32_t aAl = sm0 + (buf * 4 + 1) * TILE_ELEMS * 2;
        uint32_t aBh = sm0 + (buf * 4 + 2) * TILE_ELEMS * 2;
        uint32_t aBl = sm0 + (buf * 4 + 3) * TILE_ELEMS * 2;
        #pragma unroll
        for (int h = 0; h < 2; h++) {
            uint32_t ah[4][4], al[4][4], bh[2][4], bl[2][4];
            uint32_t a_off = (uint32_t)((wm * 64 + (lane & 15)) * (PITCH * 2)
                                        + h * 32 + (lane >> 4) * 16);
            #pragma unroll
            for (int mt = 0; mt < 4; mt++) {
                ldm_x4(ah[mt], aAh + a_off + mt * 16 * (PITCH * 2));
                ldm_x4(al[mt], aAl + a_off + mt * 16 * (PITCH * 2));
            }
            int q = lane >> 3;
            uint32_t b_off = (uint32_t)((wn * 32 + (q >> 1) * 8 + (lane & 7)) * (PITCH * 2)
                                        + h * 32 + (q & 1) * 16);
            ldm_x4(bh[0], aBh + b_off);
            ldm_x4(bh[1], aBh + b_off + 16 * (PITCH * 2));
            ldm_x4(bl[0], aBl + b_off);
            ldm_x4(bl[1], aBl + b_off + 16 * (PITCH * 2));
            #pragma unroll
            for (int mt = 0; mt < 4; mt++) {
                #pragma unroll
                for (int nt = 0; nt < 4; nt++) {
                    const uint32_t* pbh = &bh[nt >> 1][(nt & 1) * 2];
                    const uint32_t* pbl = &bl[nt >> 1][(nt & 1) * 2];
                    mma_bf16(d[mt][nt], ah[mt], pbh);
                    mma_bf16(d[mt][nt], ah[mt], pbl);
                    mma_bf16(d[mt][nt], al[mt], pbh);
                }
            }
        }
    };

    ldg_chunk(0);
    sts_chunk(0);
    __syncthreads();
    for (int c = 0; c < nc; c++) {
        if (c + 1 < nc) ldg_chunk(c + 1);
        compute(c & 1);
        if (c + 1 < nc) sts_chunk((c + 1) & 1);
        __syncthreads();
    }

    if (stage == 0) {
        // write bf16 hi/lo into unified g_f [m][256] (qf cols 0-127, vf 128-255)
        #pragma unroll
        for (int mt = 0; mt < 4; mt++) {
            int m = m0 + wm * 64 + mt * 16 + gid;
            #pragma unroll
            for (int nt = 0; nt < 4; nt++) {
                int cc = wn * 32 + nt * 8 + tg * 2;
                int gcol = by * 128 + cc;
                float bx = bias[cc], byv = bias[cc + 1];
                float v00 = d[mt][nt][0] + bx, v01 = d[mt][nt][1] + byv;
                float v10 = d[mt][nt][2] + bx, v11 = d[mt][nt][3] + byv;
                __nv_bfloat16 h0, l0, h1, l1;
                split_bf16(v00, h0, l0); split_bf16(v01, h1, l1);
                __nv_bfloat162 hp0 = {h0, h1}, lp0 = {l0, l1};
                split_bf16(v10, h0, l0); split_bf16(v11, h1, l1);
                __nv_bfloat162 hp1 = {h0, h1}, lp1 = {l0, l1};
                *(__nv_bfloat162*)&g_fh[(size_t)m * 256 + gcol] = hp0;
                *(__nv_bfloat162*)&g_fl[(size_t)m * 256 + gcol] = lp0;
                *(__nv_bfloat162*)&g_fh[(size_t)(m + 8) * 256 + gcol] = hp1;
                *(__nv_bfloat162*)&g_fl[(size_t)(m + 8) * 256 + gcol] = lp1;
            }
        }
    } else if (stage == 1) {
        // write fp32 q|off -> g_qoff, k|v -> g_kv, + bias
        #pragma unroll
        for (int mt = 0; mt < 4; mt++) {
            int m = m0 + wm * 64 + mt * 16 + gid;
            #pragma unroll
            for (int nt = 0; nt < 4; nt++) {
                int gc = by * 128 + wn * 32 + nt * 8 + tg * 2;
                if (gc >= 224) continue;
                float bx = g_bg[gc], byv = g_bg[gc + 1];
                float2 lo = make_float2(d[mt][nt][0] + bx, d[mt][nt][1] + byv);
                float2 hi = make_float2(d[mt][nt][2] + bx, d[mt][nt][3] + byv);
                if (gc < 80) {
                    *(float2*)(g_qoff + (size_t)m * 80 + gc) = lo;
                    *(float2*)(g_qoff + (size_t)(m + 8) * 80 + gc) = hi;
                } else {
                    *(float2*)(g_kv + (size_t)m * 144 + gc - 80) = lo;
                    *(float2*)(g_kv + (size_t)(m + 8) * 144 + gc - 80) = hi;
                }
            }
        }
    } else {
        int bidx = m0 >> 12;
        int pixbase = (m0 & 4095) + wm * 64;
        #pragma unroll
        for (int nt = 0; nt < 4; nt++) {
            int oc = by * 128 + wn * 32 + nt * 8 + tg * 2;
            float inv0 = rsqrtf(rvar[oc] + 1e-5f);
            float sc0 = gamma[oc] * inv0;
            float sh0 = beta[oc] - rmean[oc] * sc0;
            float inv1 = rsqrtf(rvar[oc + 1] + 1e-5f);
            float sc1 = gamma[oc + 1] * inv1;
            float sh1 = beta[oc + 1] - rmean[oc + 1] * sc1;
            float* o0 = out + ((size_t)(bidx * 256 + oc)) * NPIX;
            float* o1 = out + ((size_t)(bidx * 256 + oc + 1)) * NPIX;
            #pragma unroll
            for (int mt = 0; mt < 4; mt++) {
                int pix = pixbase + mt * 16 + gid;
                o0[pix]     = fmaxf(d[mt][nt][0] * sc0 + sh0, 0.f);
                o1[pix]     = fmaxf(d[mt][nt][1] * sc1 + sh1, 0.f);
                o0[pix + 8] = fmaxf(d[mt][nt][2] * sc0 + sh0, 0.f);
                o1[pix + 8] = fmaxf(d[mt][nt][3] * sc1 + sh1, 0.f);
            }
        }
    }
}

// ---------------- deformable point attention (2 warps / query) ----------
__global__ void __launch_bounds__(512) attention_kernel()
{
    __shared__ int    sIdx[8][128];
    __shared__ float  sW  [8][128];
    __shared__ float  sLogit[8][32];
    __shared__ float  sAttn[8][32];
    __shared__ float4 sPart[8][32];
    int tid = threadIdx.x;
    int warp = tid >> 5, lane = tid & 31;
    int q = warp & 7, half = warp >> 3;
    int m = blockIdx.x * 8 + q;
    int b = m >> 12;
    int n = m & (NPIX - 1);

    const float* row = g_qoff + (size_t)m * 80;

    // per-lane (point = lane) offsets -> 4 taps (computed by both pair warps)
    float2 d = *(const float2*)(row + 16 + 2 * lane);
    float sx = (float)(n & 63) + d.x;
    float sy = (float)(n >> 6) + d.y;
    float x0f = floorf(sx), y0f = floorf(sy);
    float wx = sx - x0f,    wy = sy - y0f;
    int ix0 = min(max((int)x0f, 0), WL - 1);
    int ix1 = min(max((int)x0f + 1, 0), WL - 1);
    int iy0 = min(max((int)y0f, 0), HL - 1);
    int iy1 = min(max((int)y0f + 1, 0), HL - 1);
    int g00 = (iy0 * WL + ix0) * 36, g01 = (iy0 * WL + ix1) * 36;
    int g10 = (iy1 * WL + ix0) * 36, g11 = (iy1 * WL + ix1) * 36;
    float w00 = (1.f - wx) * (1.f - wy), w01 = wx * (1.f - wy);
    float w10 = (1.f - wx) * wy,         w11 = wx * wy;

    int cq = lane & 3;
    int oct = lane >> 2;
    float4 qv = *(const float4*)(row + 4 * cq);
    const float4* kvb = (const float4*)(g_kv + (size_t)b * NPIX * 144);

    // phase 1 split: this warp handles point groups {half*2, half*2+1}
    #pragma unroll
    for (int gi = 0; gi < 2; gi++) {
        int g = half * 2 + gi;
        int src = oct + 8 * g;
        int G0 = __shfl_sync(0xffffffffu, g00, src);
        int G1 = __shfl_sync(0xffffffffu, g01, src);
        int G2 = __shfl_sync(0xffffffffu, g10, src);
        int G3 = __shfl_sync(0xffffffffu, g11, src);
        float W0 = __shfl_sync(0xffffffffu, w00, src);
        float W1 = __shfl_sync(0xffffffffu, w01, src);
        float W2 = __shfl_sync(0xffffffffu, w10, src);
        float W3 = __shfl_sync(0xffffffffu, w11, src);
        float4 k0 = kvb[G0 + cq];
        float4 k1 = kvb[G1 + cq];
        float4 k2 = kvb[G2 + cq];
        float4 k3 = kvb[G3 + cq];
        float ksx = W0 * k0.x + W1 * k1.x + W2 * k2.x + W3 * k3.x;
        float ksy = W0 * k0.y + W1 * k1.y + W2 * k2.y + W3 * k3.y;
        float ksz = W0 * k0.z + W1 * k1.z + W2 * k2.z + W3 * k3.z;
        float ksw = W0 * k0.w + W1 * k1.w + W2 * k2.w + W3 * k3.w;
        float part = qv.x * ksx + qv.y * ksy + qv.z * ksz + qv.w * ksw;
        part += __shfl_xor_sync(0xffffffffu, part, 1);
        part += __shfl_xor_sync(0xffffffffu, part, 2);
        if (cq == 0) sLogit[q][src] = part * 0.25f;   // 1/sqrt(16)
        int   Gq = (cq == 0) ? G0 : (cq == 1) ? G1 : (cq == 2) ? G2 : G3;
        float Wq = (cq == 0) ? W0 : (cq == 1) ? W1 : (cq == 2) ? W2 : W3;
        sIdx[q][src * 4 + cq] = Gq;
        sW  [q][src * 4 + cq] = Wq;
    }
    __syncthreads();

    // softmax over 32 points (both pair warps compute identically)
    float lg = sLogit[q][lane];
    float mx = lg;
    #pragma unroll
    for (int s = 16; s; s >>= 1) mx = fmaxf(mx, __shfl_xor_sync(0xffffffffu, mx, s));
    float e = expf(lg - mx);
    float sum = e;
    #pragma unroll
    for (int s = 16; s; s >>= 1) sum += __shfl_xor_sync(0xffffffffu, sum, s);
    sAttn[q][lane] = e / sum;
    __syncwarp();

    // phase 2: this warp gathers taps [half*64, half*64+64)
    float4 acc = make_float4(0.f, 0.f, 0.f, 0.f);
    int base = half * 64;
    #pragma unroll 4
    for (int t = 0; t < 64; t += 4) {
        int tt = base + t;
        int4   i4 = *(const int4*)&sIdx[q][tt];
        float4 w4 = *(const float4*)&sW[q][tt];
        float a = sAttn[q][tt >> 2];
        w4.x *= a; w4.y *= a; w4.z *= a; w4.w *= a;
        float4 v0 = kvb[i4.x + 4 + lane];
        float4 v1 = kvb[i4.y + 4 + lane];
        float4 v2 = kvb[i4.z + 4 + lane];
        float4 v3 = kvb[i4.w + 4 + lane];
        acc.x += w4.x * v0.x + w4.y * v1.x + w4.z * v2.x + w4.w * v3.x;
        acc.y += w4.x * v0.y + w4.y * v1.y + w4.z * v2.y + w4.w * v3.y;
        acc.z += w4.x * v0.z + w4.y * v1.z + w4.z * v2.z + w4.w * v3.z;
        acc.w += w4.x * v0.w + w4.y * v1.w + w4.z * v2.w + w4.w * v3.w;
    }
    if (half) sPart[q][lane] = acc;
    __syncthreads();
    if (!half) {
        float4 p = sPart[q][lane];
        acc.x += p.x; acc.y += p.y; acc.z += p.z; acc.w += p.w;
        size_t obase = (size_t)m * 128 + lane * 4;
        __nv_bfloat16 hv[4], lv[4];
        split_bf16(acc.x, hv[0], lv[0]);
        split_bf16(acc.y, hv[1], lv[1]);
        split_bf16(acc.z, hv[2], lv[2]);
        split_bf16(acc.w, hv[3], lv[3]);
        *(uint2*)&g_attn_h[obase] = *(uint2*)hv;
        *(uint2*)&g_attn_l[obase] = *(uint2*)lv;
    }
}

// ---------------- launch ------------------------------------------------
extern "C" void kernel_launch(void* const* d_in, const int* in_sizes, int n_in,
                              void* d_out, int out_size) {
    const float* low   = (const float*)d_in[0];
    const float* high  = (const float*)d_in[1];
    const float* W1    = (const float*)d_in[2];
    const float* b1    = (const float*)d_in[3];
    const float* W2    = (const float*)d_in[4];
    const float* b2    = (const float*)d_in[5];
    const float* Wq    = (const float*)d_in[6];
    const float* bq    = (const float*)d_in[7];
    const float* Wk    = (const float*)d_in[8];
    const float* bk    = (const float*)d_in[9];
    const float* Wv    = (const float*)d_in[10];
    const float* bv    = (const float*)d_in[11];
    const float* Woff  = (const float*)d_in[12];
    const float* boff  = (const float*)d_in[13];
    const float* Wb    = (const float*)d_in[14];
    const float* gamma = (const float*)d_in[15];
    const float* beta  = (const float*)d_in[16];
    const float* rmean = (const float*)d_in[17];
    const float* rvar  = (const float*)d_in[18];
    float* out = (float*)d_out;

    const int HMMA_SMEM = 2 * 4 * TILE_ELEMS * 2;  // 81920 bytes
    cudaFuncSetAttribute(hmma_kernel, cudaFuncAttributeMaxDynamicSharedMemorySize, HMMA_SMEM);

    prep_kernel<<<4160, 256>>>(high, low, W1, W2, Wb,
                               Wq, bq, Woff, boff, Wk, bk, Wv, bv);
    hmma_kernel<<<dim3(64, 2), 256, HMMA_SMEM>>>(
        0, b1, b2, nullptr, nullptr, nullptr, nullptr, nullptr);
    hmma_kernel<<<dim3(64, 2), 256, HMMA_SMEM>>>(
        1, nullptr, nullptr, nullptr, nullptr, nullptr, nullptr, nullptr);
    attention_kernel<<<MTOT / 8, 512>>>();
    hmma_kernel<<<dim3(64, 2), 256, HMMA_SMEM>>>(
        2, nullptr, nullptr, gamma, beta, rmean, rvar, out);
}

// round 7
// speedup vs baseline: 2.4350x; 1.0395x over previous
#include <cuda_runtime.h>
#include <cuda_bf16.h>
#include <math.h>
#include <stdint.h>

// ---------------- problem constants ----------------
#define NB   2
#define CH   256
#define INC  128
#define ITC  16
#define NPT  32
#define HL   64
#define WL   64
#define NPIX 4096
#define HH   32
#define WH   32
#define MTOT (NB * NPIX)   // 8192 rows (batch folded into M)

// ---------------- scratch (__device__ globals, no allocs) ----------------
__device__ __align__(16) __nv_bfloat16 g_c1h[MTOT * 512];  // cat1 hi
__device__ __align__(16) __nv_bfloat16 g_c1l[MTOT * 512];  // cat1 lo
__device__ __align__(16) __nv_bfloat16 g_fh [MTOT * 256];  // qf|vf hi
__device__ __align__(16) __nv_bfloat16 g_fl [MTOT * 256];  // qf|vf lo
__device__ __align__(16) float g_qoff[MTOT * 80];          // q[16] | off[64] fp32
__device__ __align__(16) __nv_bfloat16 g_kvb[MTOT * 144];  // k[16] | v[128] bf16 (288B rows)
__device__ __align__(16) __nv_bfloat16 g_attn_h[MTOT * 128];
__device__ __align__(16) __nv_bfloat16 g_attn_l[MTOT * 128];
__device__ __align__(16) __nv_bfloat16 g_W1h[128 * 512], g_W1l[128 * 512];
__device__ __align__(16) __nv_bfloat16 g_W2h[128 * 256], g_W2l[128 * 256];
__device__ __align__(16) __nv_bfloat16 g_Wbh[256 * 384], g_Wbl[256 * 384];
__device__ __align__(16) __nv_bfloat16 g_Wgh[256 * 256], g_Wgl[256 * 256];  // block-diag [q;off;k;v]
__device__ float g_bg[256];

// ---------------- mma.sync helpers ----------------
__device__ __forceinline__ uint32_t smem_u32(const void* p) {
    uint32_t a;
    asm("{ .reg .u64 t; cvta.to.shared.u64 t, %1; cvt.u32.u64 %0, t; }" : "=r"(a) : "l"(p));
    return a;
}
__device__ __forceinline__ void ldm_x4(uint32_t* r, uint32_t addr) {
    asm volatile("ldmatrix.sync.aligned.m8n8.x4.shared.b16 {%0,%1,%2,%3}, [%4];"
        : "=r"(r[0]), "=r"(r[1]), "=r"(r[2]), "=r"(r[3]) : "r"(addr));
}
__device__ __forceinline__ void mma_bf16(float* d, const uint32_t* a, const uint32_t* b) {
    asm volatile("mma.sync.aligned.m16n8k16.row.col.f32.bf16.bf16.f32 "
        "{%0,%1,%2,%3}, {%4,%5,%6,%7}, {%8,%9}, {%0,%1,%2,%3};"
        : "+f"(d[0]), "+f"(d[1]), "+f"(d[2]), "+f"(d[3])
        : "r"(a[0]), "r"(a[1]), "r"(a[2]), "r"(a[3]), "r"(b[0]), "r"(b[1]));
}

__device__ __forceinline__ void split_bf16(float x, __nv_bfloat16& h, __nv_bfloat16& l) {
    h = __float2bfloat16(x);
    l = __float2bfloat16(x - __bfloat162float(h));
}

// ---------------- prep: upsample + transpose -> bf16 splits; weight packing --
__global__ void __launch_bounds__(256) prep_kernel(
    const float* __restrict__ high, const float* __restrict__ low,
    const float* __restrict__ W1, const float* __restrict__ W2,
    const float* __restrict__ Wb,
    const float* __restrict__ Wq, const float* __restrict__ bq,
    const float* __restrict__ Woff, const float* __restrict__ boff,
    const float* __restrict__ Wk, const float* __restrict__ bk,
    const float* __restrict__ Wv, const float* __restrict__ bv)
{
    int blk = blockIdx.x;
    int tid = threadIdx.x;

    if (blk >= 4096) {
        for (int e = (blk - 4096) * 256 + tid; e < 262400; e += 16384) {
            if (e < 65536) {
                split_bf16(W1[e], g_W1h[e], g_W1l[e]);
            } else if (e < 98304) {
                int t = e - 65536;
                split_bf16(W2[t], g_W2h[t], g_W2l[t]);
            } else if (e < 196608) {
                int t = e - 98304;
                split_bf16(Wb[t], g_Wbh[t], g_Wbl[t]);
            } else if (e < 262144) {
                int t = e - 196608;
                int r = t >> 8, k = t & 255;
                float v = 0.f;
                if (r < 16)       { if (k < 128)  v = Wq[r * 128 + k]; }
                else if (r < 80)  { if (k < 128)  v = Woff[(r - 16) * 128 + k]; }
                else if (r < 96)  { if (k >= 128) v = Wk[(r - 80) * 128 + k - 128]; }
                else if (r < 224) { if (k >= 128) v = Wv[(r - 96) * 128 + k - 128]; }
                split_bf16(v, g_Wgh[t], g_Wgl[t]);
            } else {
                int i = e - 262144;
                float v = 0.f;
                if (i < 16)       v = bq[i];
                else if (i < 80)  v = boff[i - 16];
                else if (i < 96)  v = bk[i - 80];
                else if (i < 224) v = bv[i - 96];
                g_bg[i] = v;
            }
        }
        return;
    }

    int part = blk >> 11;          // 0: high_up, 1: low
    int r = blk & 2047;
    int b = r >> 10;
    int r2 = r & 1023;
    int pt = r2 >> 3;
    int ct = r2 & 7;
    int p0 = pt * 32;
    int c0 = ct * 32;

    __shared__ float s[32][33];
    int px = tid & 31;
    int cq = tid >> 5;

    if (part == 1) {
        #pragma unroll
        for (int i = 0; i < 4; i++) {
            int c = cq * 4 + i;
            s[c][px] = low[((size_t)(b * CH + c0 + c)) * NPIX + p0 + px];
        }
    } else {
        int y = p0 >> 6;
        int xb = p0 & 63;
        float fy = y * 0.5f - 0.25f;
        float y0f = floorf(fy);
        float wy = fy - y0f;
        int iy0 = min(max((int)y0f, 0), HH - 1);
        int iy1 = min(max((int)y0f + 1, 0), HH - 1);
        int x = xb + px;
        float fx = x * 0.5f - 0.25f;
        float x0f = floorf(fx);
        float wx = fx - x0f;
        int ix0 = min(max((int)x0f, 0), WH - 1);
        int ix1 = min(max((int)x0f + 1, 0), WH - 1);
        #pragma unroll
        for (int i = 0; i < 4; i++) {
            int c = cq * 4 + i;
            const float* src = high + ((size_t)(b * CH + c0 + c)) * (HH * WH);
            float v00 = src[iy0 * WH + ix0], v01 = src[iy0 * WH + ix1];
            float v10 = src[iy1 * WH + ix0], v11 = src[iy1 * WH + ix1];
            s[c][px] = (1.f - wx) * (1.f - wy) * v00 + wx * (1.f - wy) * v01
                     + (1.f - wx) * wy * v10 + wx * wy * v11;
        }
    }
    __syncthreads();

    int cc = tid & 31;
    int pq = tid >> 5;
    int base_c = (part == 0 ? c0 : 256 + c0) + cc;
    #pragma unroll
    for (int i = 0; i < 4; i++) {
        int pp = pq * 4 + i;
        size_t idx = ((size_t)(b * NPIX + p0 + pp)) * 512 + base_c;
        __nv_bfloat16 h, l;
        split_bf16(s[cc][pp], h, l);
        g_c1h[idx] = h;
        g_c1l[idx] = l;
    }
}

// ---------------- bf16x3 mma.sync GEMM (stages 0,1,2) --------------------
#define PITCH 40
#define TILE_ELEMS (128 * PITCH)

__global__ void __launch_bounds__(256) hmma_kernel(
    int stage,
    const float* __restrict__ bias0, const float* __restrict__ bias1,
    const float* __restrict__ gamma, const float* __restrict__ beta,
    const float* __restrict__ rmean, const float* __restrict__ rvar,
    float* __restrict__ out)
{
    extern __shared__ __nv_bfloat16 sm[];
    int tid = threadIdx.x;
    int wid = tid >> 5, lane = tid & 31;
    int wm = wid >> 2, wn = wid & 3;
    int gid = lane >> 2, tg = lane & 3;
    int m0 = blockIdx.x * 128;
    int by = blockIdx.y;

    int K, ldb;
    const __nv_bfloat16 *Bh, *Bl;
    const float* bias = nullptr;
    if (stage == 0) {
        if (by == 0) { K = 512; Bh = g_W1h; Bl = g_W1l; ldb = 512; bias = bias0; }
        else         { K = 256; Bh = g_W2h; Bl = g_W2l; ldb = 256; bias = bias1; }
    } else if (stage == 1) {
        K = 256; ldb = 256;
        Bh = g_Wgh + (size_t)by * 128 * 256;
        Bl = g_Wgl + (size_t)by * 128 * 256;
    } else {
        K = 384; ldb = 384;
        Bh = g_Wbh + (size_t)by * 128 * 384;
        Bl = g_Wbl + (size_t)by * 128 * 384;
    }
    int nc = K >> 5;

    float d[4][4][4];
    #pragma unroll
    for (int i = 0; i < 4; i++)
        #pragma unroll
        for (int j = 0; j < 4; j++)
            #pragma unroll
            for (int k = 0; k < 4; k++) d[i][j][k] = 0.f;

    int seg = tid & 3;
    int r0 = tid >> 2;

    uint4 stg[8];
    auto ldg_chunk = [&](int c) {
        const __nv_bfloat16 *Ah_src, *Al_src;
        int lda, colA;
        if (stage == 0)      { Ah_src = g_c1h; Al_src = g_c1l; lda = 512; colA = c * 32; }
        else if (stage == 1) { Ah_src = g_fh;  Al_src = g_fl;  lda = 256; colA = c * 32; }
        else if (c < 4)      { Ah_src = g_attn_h; Al_src = g_attn_l; lda = 128; colA = c * 32; }
        else                 { Ah_src = g_c1h; Al_src = g_c1l; lda = 512; colA = (c - 4) * 32; }
        const __nv_bfloat16* ah = Ah_src + (size_t)m0 * lda + colA + seg * 8;
        const __nv_bfloat16* al = Al_src + (size_t)m0 * lda + colA + seg * 8;
        const __nv_bfloat16* bh = Bh + c * 32 + seg * 8;
        const __nv_bfloat16* bl = Bl + c * 32 + seg * 8;
        stg[0] = *(const uint4*)(ah + (size_t)r0 * lda);
        stg[1] = *(const uint4*)(ah + (size_t)(r0 + 64) * lda);
        stg[2] = *(const uint4*)(al + (size_t)r0 * lda);
        stg[3] = *(const uint4*)(al + (size_t)(r0 + 64) * lda);
        stg[4] = *(const uint4*)(bh + (size_t)r0 * ldb);
        stg[5] = *(const uint4*)(bh + (size_t)(r0 + 64) * ldb);
        stg[6] = *(const uint4*)(bl + (size_t)r0 * ldb);
        stg[7] = *(const uint4*)(bl + (size_t)(r0 + 64) * ldb);
    };
    auto sts_chunk = [&](int buf) {
        #pragma unroll
        for (int t = 0; t < 4; t++) {
            __nv_bfloat16* base = sm + (buf * 4 + t) * TILE_ELEMS;
            *(uint4*)(base + r0 * PITCH + seg * 8)         = stg[t * 2];
            *(uint4*)(base + (r0 + 64) * PITCH + seg * 8)  = stg[t * 2 + 1];
        }
    };

    uint32_t sm0 = smem_u32(sm);
    auto compute = [&](int buf) {
        uint32_t aAh = sm0 + (buf * 4 + 0) * TILE_ELEMS * 2;
        uint32_t aAl = sm0 + (buf * 4 + 1) * TILE_ELEMS * 2;
        uint32_t aBh = sm0 + (buf * 4 + 2) * TILE_ELEMS * 2;
        uint32_t aBl = sm0 + (buf * 4 + 3) * TILE_ELEMS * 2;
        #pragma unroll
        for (int h = 0; h < 2; h++) {
            uint32_t ah[4][4], al[4][4], bh[2][4], bl[2][4];
            uint32_t a_off = (uint32_t)((wm * 64 + (lane & 15)) * (PITCH * 2)
                                        + h * 32 + (lane >> 4) * 16);
            #pragma unroll
            for (int mt = 0; mt < 4; mt++) {
                ldm_x4(ah[mt], aAh + a_off + mt * 16 * (PITCH * 2));
                ldm_x4(al[mt], aAl + a_off + mt * 16 * (PITCH * 2));
            }
            int q = lane >> 3;
            uint32_t b_off = (uint32_t)((wn * 32 + (q >> 1) * 8 + (lane & 7)) * (PITCH * 2)
                                        + h * 32 + (q & 1) * 16);
            ldm_x4(bh[0], aBh + b_off);
            ldm_x4(bh[1], aBh + b_off + 16 * (PITCH * 2));
            ldm_x4(bl[0], aBl + b_off);
            ldm_x4(bl[1], aBl + b_off + 16 * (PITCH * 2));
            #pragma unroll
            for (int mt = 0; mt < 4; mt++) {
                #pragma unroll
                for (int nt = 0; nt < 4; nt++) {
                    const uint32_t* pbh = &bh[nt >> 1][(nt & 1) * 2];
                    const uint32_t* pbl = &bl[nt >> 1][(nt & 1) * 2];
                    mma_bf16(d[mt][nt], ah[mt], pbh);
                    mma_bf16(d[mt][nt], ah[mt], pbl);
                    mma_bf16(d[mt][nt], al[mt], pbh);
                }
            }
        }
    };

    ldg_chunk(0);
    sts_chunk(0);
    __syncthreads();
    for (int c = 0; c < nc; c++) {
        if (c + 1 < nc) ldg_chunk(c + 1);
        compute(c & 1);
        if (c + 1 < nc) sts_chunk((c + 1) & 1);
        __syncthreads();
    }

    if (stage == 0) {
        #pragma unroll
        for (int mt = 0; mt < 4; mt++) {
            int m = m0 + wm * 64 + mt * 16 + gid;
            #pragma unroll
            for (int nt = 0; nt < 4; nt++) {
                int cc = wn * 32 + nt * 8 + tg * 2;
                int gcol = by * 128 + cc;
                float bx = bias[cc], byv = bias[cc + 1];
                float v00 = d[mt][nt][0] + bx, v01 = d[mt][nt][1] + byv;
                float v10 = d[mt][nt][2] + bx, v11 = d[mt][nt][3] + byv;
                __nv_bfloat16 h0, l0, h1, l1;
                split_bf16(v00, h0, l0); split_bf16(v01, h1, l1);
                __nv_bfloat162 hp0 = {h0, h1}, lp0 = {l0, l1};
                split_bf16(v10, h0, l0); split_bf16(v11, h1, l1);
                __nv_bfloat162 hp1 = {h0, h1}, lp1 = {l0, l1};
                *(__nv_bfloat162*)&g_fh[(size_t)m * 256 + gcol] = hp0;
                *(__nv_bfloat162*)&g_fl[(size_t)m * 256 + gcol] = lp0;
                *(__nv_bfloat162*)&g_fh[(size_t)(m + 8) * 256 + gcol] = hp1;
                *(__nv_bfloat162*)&g_fl[(size_t)(m + 8) * 256 + gcol] = lp1;
            }
        }
    } else if (stage == 1) {
        // q|off fp32 -> g_qoff; k|v bf16 -> g_kvb
        #pragma unroll
        for (int mt = 0; mt < 4; mt++) {
            int m = m0 + wm * 64 + mt * 16 + gid;
            #pragma unroll
            for (int nt = 0; nt < 4; nt++) {
                int gc = by * 128 + wn * 32 + nt * 8 + tg * 2;
                if (gc >= 224) continue;
                float bx = g_bg[gc], byv = g_bg[gc + 1];
                float2 lo = make_float2(d[mt][nt][0] + bx, d[mt][nt][1] + byv);
                float2 hi = make_float2(d[mt][nt][2] + bx, d[mt][nt][3] + byv);
                if (gc < 80) {
                    *(float2*)(g_qoff + (size_t)m * 80 + gc) = lo;
                    *(float2*)(g_qoff + (size_t)(m + 8) * 80 + gc) = hi;
                } else {
                    __nv_bfloat162 blo = __float22bfloat162_rn(lo);
                    __nv_bfloat162 bhi = __float22bfloat162_rn(hi);
                    *(__nv_bfloat162*)(g_kvb + (size_t)m * 144 + gc - 80) = blo;
                    *(__nv_bfloat162*)(g_kvb + (size_t)(m + 8) * 144 + gc - 80) = bhi;
                }
            }
        }
    } else {
        int bidx = m0 >> 12;
        int pixbase = (m0 & 4095) + wm * 64;
        #pragma unroll
        for (int nt = 0; nt < 4; nt++) {
            int oc = by * 128 + wn * 32 + nt * 8 + tg * 2;
            float inv0 = rsqrtf(rvar[oc] + 1e-5f);
            float sc0 = gamma[oc] * inv0;
            float sh0 = beta[oc] - rmean[oc] * sc0;
            float inv1 = rsqrtf(rvar[oc + 1] + 1e-5f);
            float sc1 = gamma[oc + 1] * inv1;
            float sh1 = beta[oc + 1] - rmean[oc + 1] * sc1;
            float* o0 = out + ((size_t)(bidx * 256 + oc)) * NPIX;
            float* o1 = out + ((size_t)(bidx * 256 + oc + 1)) * NPIX;
            #pragma unroll
            for (int mt = 0; mt < 4; mt++) {
                int pix = pixbase + mt * 16 + gid;
                o0[pix]     = fmaxf(d[mt][nt][0] * sc0 + sh0, 0.f);
                o1[pix]     = fmaxf(d[mt][nt][1] * sc1 + sh1, 0.f);
                o0[pix + 8] = fmaxf(d[mt][nt][2] * sc0 + sh0, 0.f);
                o1[pix + 8] = fmaxf(d[mt][nt][3] * sc1 + sh1, 0.f);
            }
        }
    }
}

// ---------------- deformable point attention (2 warps / query, bf16 kv) --
__global__ void __launch_bounds__(512) attention_kernel()
{
    __shared__ int    sIdx[8][128];
    __shared__ float  sW  [8][128];
    __shared__ float  sLogit[8][32];
    __shared__ float  sAttn[8][32];
    __shared__ float4 sPart[8][32];
    int tid = threadIdx.x;
    int warp = tid >> 5, lane = tid & 31;
    int q = warp & 7, half = warp >> 3;
    int m = blockIdx.x * 8 + q;
    int b = m >> 12;
    int n = m & (NPIX - 1);

    const float* row = g_qoff + (size_t)m * 80;

    // per-lane (point = lane) offsets -> 4 taps
    float2 d = *(const float2*)(row + 16 + 2 * lane);
    float sx = (float)(n & 63) + d.x;
    float sy = (float)(n >> 6) + d.y;
    float x0f = floorf(sx), y0f = floorf(sy);
    float wx = sx - x0f,    wy = sy - y0f;
    int ix0 = min(max((int)x0f, 0), WL - 1);
    int ix1 = min(max((int)x0f + 1, 0), WL - 1);
    int iy0 = min(max((int)y0f, 0), HL - 1);
    int iy1 = min(max((int)y0f + 1, 0), HL - 1);
    // tap indices in BYTES (row = 144 bf16 = 288 B)
    int g00 = (iy0 * WL + ix0) * 288, g01 = (iy0 * WL + ix1) * 288;
    int g10 = (iy1 * WL + ix0) * 288, g11 = (iy1 * WL + ix1) * 288;
    float w00 = (1.f - wx) * (1.f - wy), w01 = wx * (1.f - wy);
    float w10 = (1.f - wx) * wy,         w11 = wx * wy;

    int cq = lane & 3;
    int oct = lane >> 2;
    float4 qv = *(const float4*)(row + 4 * cq);
    const char* kvB = (const char*)(g_kvb + (size_t)b * NPIX * 144);

    // phase 1: this warp handles point groups {half*2, half*2+1}
    #pragma unroll
    for (int gi = 0; gi < 2; gi++) {
        int g = half * 2 + gi;
        int src = oct + 8 * g;
        int G0 = __shfl_sync(0xffffffffu, g00, src);
        int G1 = __shfl_sync(0xffffffffu, g01, src);
        int G2 = __shfl_sync(0xffffffffu, g10, src);
        int G3 = __shfl_sync(0xffffffffu, g11, src);
        float W0 = __shfl_sync(0xffffffffu, w00, src);
        float W1 = __shfl_sync(0xffffffffu, w01, src);
        float W2 = __shfl_sync(0xffffffffu, w10, src);
        float W3 = __shfl_sync(0xffffffffu, w11, src);
        // k: 4 bf16 channels per quad lane (8 B)
        uint2 kp0 = *(const uint2*)(kvB + G0 + cq * 8);
        uint2 kp1 = *(const uint2*)(kvB + G1 + cq * 8);
        uint2 kp2 = *(const uint2*)(kvB + G2 + cq * 8);
        uint2 kp3 = *(const uint2*)(kvB + G3 + cq * 8);
        float2 a0 = __bfloat1622float2(*(__nv_bfloat162*)&kp0.x);
        float2 b0 = __bfloat1622float2(*(__nv_bfloat162*)&kp0.y);
        float2 a1 = __bfloat1622float2(*(__nv_bfloat162*)&kp1.x);
        float2 b1 = __bfloat1622float2(*(__nv_bfloat162*)&kp1.y);
        float2 a2 = __bfloat1622float2(*(__nv_bfloat162*)&kp2.x);
        float2 b2 = __bfloat1622float2(*(__nv_bfloat162*)&kp2.y);
        float2 a3 = __bfloat1622float2(*(__nv_bfloat162*)&kp3.x);
        float2 b3 = __bfloat1622float2(*(__nv_bfloat162*)&kp3.y);
        float ksx = W0 * a0.x + W1 * a1.x + W2 * a2.x + W3 * a3.x;
        float ksy = W0 * a0.y + W1 * a1.y + W2 * a2.y + W3 * a3.y;
        float ksz = W0 * b0.x + W1 * b1.x + W2 * b2.x + W3 * b3.x;
        float ksw = W0 * b0.y + W1 * b1.y + W2 * b2.y + W3 * b3.y;
        float part = qv.x * ksx + qv.y * ksy + qv.z * ksz + qv.w * ksw;
        part += __shfl_xor_sync(0xffffffffu, part, 1);
        part += __shfl_xor_sync(0xffffffffu, part, 2);
        if (cq == 0) sLogit[q][src] = part * 0.25f;   // 1/sqrt(16)
        int   Gq = (cq == 0) ? G0 : (cq == 1) ? G1 : (cq == 2) ? G2 : G3;
        float Wq = (cq == 0) ? W0 : (cq == 1) ? W1 : (cq == 2) ? W2 : W3;
        sIdx[q][src * 4 + cq] = Gq;
        sW  [q][src * 4 + cq] = Wq;
    }
    __syncthreads();

    // softmax over 32 points (both pair warps compute identically)
    float lg = sLogit[q][lane];
    float mx = lg;
    #pragma unroll
    for (int s = 16; s; s >>= 1) mx = fmaxf(mx, __shfl_xor_sync(0xffffffffu, mx, s));
    float e = expf(lg - mx);
    float sum = e;
    #pragma unroll
    for (int s = 16; s; s >>= 1) sum += __shfl_xor_sync(0xffffffffu, sum, s);
    sAttn[q][lane] = e / sum;
    __syncwarp();

    // phase 2: this warp gathers taps [half*64, half*64+64); 4 bf16 ch/lane
    float4 acc = make_float4(0.f, 0.f, 0.f, 0.f);
    int base = half * 64;
    int loff = 32 + lane * 8;   // v starts at byte 32 of the row
    #pragma unroll 4
    for (int t = 0; t < 64; t += 4) {
        int tt = base + t;
        int4   i4 = *(const int4*)&sIdx[q][tt];
        float4 w4 = *(const float4*)&sW[q][tt];
        float a = sAttn[q][tt >> 2];
        w4.x *= a; w4.y *= a; w4.z *= a; w4.w *= a;
        uint2 p0 = *(const uint2*)(kvB + i4.x + loff);
        uint2 p1 = *(const uint2*)(kvB + i4.y + loff);
        uint2 p2 = *(const uint2*)(kvB + i4.z + loff);
        uint2 p3 = *(const uint2*)(kvB + i4.w + loff);
        float2 v0a = __bfloat1622float2(*(__nv_bfloat162*)&p0.x);
        float2 v0b = __bfloat1622float2(*(__nv_bfloat162*)&p0.y);
        float2 v1a = __bfloat1622float2(*(__nv_bfloat162*)&p1.x);
        float2 v1b = __bfloat1622float2(*(__nv_bfloat162*)&p1.y);
        float2 v2a = __bfloat1622float2(*(__nv_bfloat162*)&p2.x);
        float2 v2b = __bfloat1622float2(*(__nv_bfloat162*)&p2.y);
        float2 v3a = __bfloat1622float2(*(__nv_bfloat162*)&p3.x);
        float2 v3b = __bfloat1622float2(*(__nv_bfloat162*)&p3.y);
        acc.x += w4.x * v0a.x + w4.y * v1a.x + w4.z * v2a.x + w4.w * v3a.x;
        acc.y += w4.x * v0a.y + w4.y * v1a.y + w4.z * v2a.y + w4.w * v3a.y;
        acc.z += w4.x * v0b.x + w4.y * v1b.x + w4.z * v2b.x + w4.w * v3b.x;
        acc.w += w4.x * v0b.y + w4.y * v1b.y + w4.z * v2b.y + w4.w * v3b.y;
    }
    if (half) sPart[q][lane] = acc;
    __syncthreads();
    if (!half) {
        float4 p = sPart[q][lane];
        acc.x += p.x; acc.y += p.y; acc.z += p.z; acc.w += p.w;
        size_t obase = (size_t)m * 128 + lane * 4;
        __nv_bfloat16 hv[4], lv[4];
        split_bf16(acc.x, hv[0], lv[0]);
        split_bf16(acc.y, hv[1], lv[1]);
        split_bf16(acc.z, hv[2], lv[2]);
        split_bf16(acc.w, hv[3], lv[3]);
        *(uint2*)&g_attn_h[obase] = *(uint2*)hv;
        *(uint2*)&g_attn_l[obase] = *(uint2*)lv;
    }
}

// ---------------- launch ------------------------------------------------
extern "C" void kernel_launch(void* const* d_in, const int* in_sizes, int n_in,
                              void* d_out, int out_size) {
    const float* low   = (const float*)d_in[0];
    const float* high  = (const float*)d_in[1];
    const float* W1    = (const float*)d_in[2];
    const float* b1    = (const float*)d_in[3];
    const float* W2    = (const float*)d_in[4];
    const float* b2    = (const float*)d_in[5];
    const float* Wq    = (const float*)d_in[6];
    const float* bq    = (const float*)d_in[7];
    const float* Wk    = (const float*)d_in[8];
    const float* bk    = (const float*)d_in[9];
    const float* Wv    = (const float*)d_in[10];
    const float* bv    = (const float*)d_in[11];
    const float* Woff  = (const float*)d_in[12];
    const float* boff  = (const float*)d_in[13];
    const float* Wb    = (const float*)d_in[14];
    const float* gamma = (const float*)d_in[15];
    const float* beta  = (const float*)d_in[16];
    const float* rmean = (const float*)d_in[17];
    const float* rvar  = (const float*)d_in[18];
    float* out = (float*)d_out;

    const int HMMA_SMEM = 2 * 4 * TILE_ELEMS * 2;  // 81920 bytes
    cudaFuncSetAttribute(hmma_kernel, cudaFuncAttributeMaxDynamicSharedMemorySize, HMMA_SMEM);

    prep_kernel<<<4160, 256>>>(high, low, W1, W2, Wb,
                               Wq, bq, Woff, boff, Wk, bk, Wv, bv);
    hmma_kernel<<<dim3(64, 2), 256, HMMA_SMEM>>>(
        0, b1, b2, nullptr, nullptr, nullptr, nullptr, nullptr);
    hmma_kernel<<<dim3(64, 2), 256, HMMA_SMEM>>>(
        1, nullptr, nullptr, nullptr, nullptr, nullptr, nullptr, nullptr);
    attention_kernel<<<MTOT / 8, 512>>>();
    hmma_kernel<<<dim3(64, 2), 256, HMMA_SMEM>>>(
        2, nullptr, nullptr, gamma, beta, rmean, rvar, out);
}

// round 8
// speedup vs baseline: 2.5483x; 1.0465x over previous
#include <cuda_runtime.h>
#include <cuda_bf16.h>
#include <math.h>
#include <stdint.h>

// ---------------- problem constants ----------------
#define NB   2
#define CH   256
#define INC  128
#define ITC  16
#define NPT  32
#define HL   64
#define WL   64
#define NPIX 4096
#define HH   32
#define WH   32
#define MTOT (NB * NPIX)   // 8192 rows (batch folded into M)

// ---------------- scratch (__device__ globals, no allocs) ----------------
__device__ __align__(16) __nv_bfloat16 g_c1h[MTOT * 512];  // cat1 hi
__device__ __align__(16) __nv_bfloat16 g_c1l[MTOT * 512];  // cat1 lo
__device__ __align__(16) __nv_bfloat16 g_fh [MTOT * 256];  // qf|vf hi
__device__ __align__(16) __nv_bfloat16 g_fl [MTOT * 256];  // qf|vf lo
__device__ __align__(16) float g_qoff[MTOT * 80];          // q[16] | off[64] fp32
__device__ __align__(16) __nv_bfloat16 g_kvb[MTOT * 144];  // k[16] | v[128] bf16 (288B rows)
__device__ __align__(16) __nv_bfloat16 g_attn_h[MTOT * 128];
__device__ __align__(16) __nv_bfloat16 g_attn_l[MTOT * 128];
__device__ __align__(16) __nv_bfloat16 g_W1h[128 * 512], g_W1l[128 * 512];
__device__ __align__(16) __nv_bfloat16 g_W2h[128 * 256], g_W2l[128 * 256];
__device__ __align__(16) __nv_bfloat16 g_Wbh[256 * 384], g_Wbl[256 * 384];
__device__ __align__(16) __nv_bfloat16 g_Wgh[256 * 256], g_Wgl[256 * 256];  // block-diag [q;off;k;v]
__device__ float g_bg[256];

// ---------------- mma.sync helpers ----------------
__device__ __forceinline__ uint32_t smem_u32(const void* p) {
    uint32_t a;
    asm("{ .reg .u64 t; cvta.to.shared.u64 t, %1; cvt.u32.u64 %0, t; }" : "=r"(a) : "l"(p));
    return a;
}
__device__ __forceinline__ void ldm_x4(uint32_t* r, uint32_t addr) {
    asm volatile("ldmatrix.sync.aligned.m8n8.x4.shared.b16 {%0,%1,%2,%3}, [%4];"
        : "=r"(r[0]), "=r"(r[1]), "=r"(r[2]), "=r"(r[3]) : "r"(addr));
}
__device__ __forceinline__ void mma_bf16(float* d, const uint32_t* a, const uint32_t* b) {
    asm volatile("mma.sync.aligned.m16n8k16.row.col.f32.bf16.bf16.f32 "
        "{%0,%1,%2,%3}, {%4,%5,%6,%7}, {%8,%9}, {%0,%1,%2,%3};"
        : "+f"(d[0]), "+f"(d[1]), "+f"(d[2]), "+f"(d[3])
        : "r"(a[0]), "r"(a[1]), "r"(a[2]), "r"(a[3]), "r"(b[0]), "r"(b[1]));
}

__device__ __forceinline__ void split_bf16(float x, __nv_bfloat16& h, __nv_bfloat16& l) {
    h = __float2bfloat16(x);
    l = __float2bfloat16(x - __bfloat162float(h));
}
// bf16x2 word -> two fp32 via pure bit ops (exact; no CVT pipe)
__device__ __forceinline__ float bfu_lo(uint32_t u) { return __uint_as_float(u << 16); }
__device__ __forceinline__ float bfu_hi(uint32_t u) { return __uint_as_float(u & 0xffff0000u); }

// ---------------- prep: upsample + transpose -> bf16 splits; weight packing --
__global__ void __launch_bounds__(256) prep_kernel(
    const float* __restrict__ high, const float* __restrict__ low,
    const float* __restrict__ W1, const float* __restrict__ W2,
    const float* __restrict__ Wb,
    const float* __restrict__ Wq, const float* __restrict__ bq,
    const float* __restrict__ Woff, const float* __restrict__ boff,
    const float* __restrict__ Wk, const float* __restrict__ bk,
    const float* __restrict__ Wv, const float* __restrict__ bv)
{
    int blk = blockIdx.x;
    int tid = threadIdx.x;

    if (blk >= 4096) {
        for (int e = (blk - 4096) * 256 + tid; e < 262400; e += 16384) {
            if (e < 65536) {
                split_bf16(W1[e], g_W1h[e], g_W1l[e]);
            } else if (e < 98304) {
                int t = e - 65536;
                split_bf16(W2[t], g_W2h[t], g_W2l[t]);
            } else if (e < 196608) {
                int t = e - 98304;
                split_bf16(Wb[t], g_Wbh[t], g_Wbl[t]);
            } else if (e < 262144) {
                int t = e - 196608;
                int r = t >> 8, k = t & 255;
                float v = 0.f;
                if (r < 16)       { if (k < 128)  v = Wq[r * 128 + k]; }
                else if (r < 80)  { if (k < 128)  v = Woff[(r - 16) * 128 + k]; }
                else if (r < 96)  { if (k >= 128) v = Wk[(r - 80) * 128 + k - 128]; }
                else if (r < 224) { if (k >= 128) v = Wv[(r - 96) * 128 + k - 128]; }
                split_bf16(v, g_Wgh[t], g_Wgl[t]);
            } else {
                int i = e - 262144;
                float v = 0.f;
                if (i < 16)       v = bq[i];
                else if (i < 80)  v = boff[i - 16];
                else if (i < 96)  v = bk[i - 80];
                else if (i < 224) v = bv[i - 96];
                g_bg[i] = v;
            }
        }
        return;
    }

    int part = blk >> 11;          // 0: high_up, 1: low
    int r = blk & 2047;
    int b = r >> 10;
    int r2 = r & 1023;
    int pt = r2 >> 3;
    int ct = r2 & 7;
    int p0 = pt * 32;
    int c0 = ct * 32;

    __shared__ float s[32][33];
    int px = tid & 31;
    int cq = tid >> 5;

    if (part == 1) {
        #pragma unroll
        for (int i = 0; i < 4; i++) {
            int c = cq * 4 + i;
            s[c][px] = low[((size_t)(b * CH + c0 + c)) * NPIX + p0 + px];
        }
    } else {
        int y = p0 >> 6;
        int xb = p0 & 63;
        float fy = y * 0.5f - 0.25f;
        float y0f = floorf(fy);
        float wy = fy - y0f;
        int iy0 = min(max((int)y0f, 0), HH - 1);
        int iy1 = min(max((int)y0f + 1, 0), HH - 1);
        int x = xb + px;
        float fx = x * 0.5f - 0.25f;
        float x0f = floorf(fx);
        float wx = fx - x0f;
        int ix0 = min(max((int)x0f, 0), WH - 1);
        int ix1 = min(max((int)x0f + 1, 0), WH - 1);
        #pragma unroll
        for (int i = 0; i < 4; i++) {
            int c = cq * 4 + i;
            const float* src = high + ((size_t)(b * CH + c0 + c)) * (HH * WH);
            float v00 = src[iy0 * WH + ix0], v01 = src[iy0 * WH + ix1];
            float v10 = src[iy1 * WH + ix0], v11 = src[iy1 * WH + ix1];
            s[c][px] = (1.f - wx) * (1.f - wy) * v00 + wx * (1.f - wy) * v01
                     + (1.f - wx) * wy * v10 + wx * wy * v11;
        }
    }
    __syncthreads();

    int cc = tid & 31;
    int pq = tid >> 5;
    int base_c = (part == 0 ? c0 : 256 + c0) + cc;
    #pragma unroll
    for (int i = 0; i < 4; i++) {
        int pp = pq * 4 + i;
        size_t idx = ((size_t)(b * NPIX + p0 + pp)) * 512 + base_c;
        __nv_bfloat16 h, l;
        split_bf16(s[cc][pp], h, l);
        g_c1h[idx] = h;
        g_c1l[idx] = l;
    }
}

// ---------------- bf16x3 mma.sync GEMM (stages 0,1,2) --------------------
#define PITCH 40
#define TILE_ELEMS (128 * PITCH)

__global__ void __launch_bounds__(256) hmma_kernel(
    int stage,
    const float* __restrict__ bias0, const float* __restrict__ bias1,
    const float* __restrict__ gamma, const float* __restrict__ beta,
    const float* __restrict__ rmean, const float* __restrict__ rvar,
    float* __restrict__ out)
{
    extern __shared__ __nv_bfloat16 sm[];
    int tid = threadIdx.x;
    int wid = tid >> 5, lane = tid & 31;
    int wm = wid >> 2, wn = wid & 3;
    int gid = lane >> 2, tg = lane & 3;
    int m0 = blockIdx.x * 128;
    int by = blockIdx.y;

    int K, ldb;
    const __nv_bfloat16 *Bh, *Bl;
    const float* bias = nullptr;
    if (stage == 0) {
        if (by == 0) { K = 512; Bh = g_W1h; Bl = g_W1l; ldb = 512; bias = bias0; }
        else         { K = 256; Bh = g_W2h; Bl = g_W2l; ldb = 256; bias = bias1; }
    } else if (stage == 1) {
        K = 256; ldb = 256;
        Bh = g_Wgh + (size_t)by * 128 * 256;
        Bl = g_Wgl + (size_t)by * 128 * 256;
    } else {
        K = 384; ldb = 384;
        Bh = g_Wbh + (size_t)by * 128 * 384;
        Bl = g_Wbl + (size_t)by * 128 * 384;
    }
    int nc = K >> 5;

    float d[4][4][4];
    #pragma unroll
    for (int i = 0; i < 4; i++)
        #pragma unroll
        for (int j = 0; j < 4; j++)
            #pragma unroll
            for (int k = 0; k < 4; k++) d[i][j][k] = 0.f;

    int seg = tid & 3;
    int r0 = tid >> 2;

    uint4 stg[8];
    auto ldg_chunk = [&](int c) {
        const __nv_bfloat16 *Ah_src, *Al_src;
        int lda, colA;
        if (stage == 0)      { Ah_src = g_c1h; Al_src = g_c1l; lda = 512; colA = c * 32; }
        else if (stage == 1) { Ah_src = g_fh;  Al_src = g_fl;  lda = 256; colA = c * 32; }
        else if (c < 4)      { Ah_src = g_attn_h; Al_src = g_attn_l; lda = 128; colA = c * 32; }
        else                 { Ah_src = g_c1h; Al_src = g_c1l; lda = 512; colA = (c - 4) * 32; }
        const __nv_bfloat16* ah = Ah_src + (size_t)m0 * lda + colA + seg * 8;
        const __nv_bfloat16* al = Al_src + (size_t)m0 * lda + colA + seg * 8;
        const __nv_bfloat16* bh = Bh + c * 32 + seg * 8;
        const __nv_bfloat16* bl = Bl + c * 32 + seg * 8;
        stg[0] = *(const uint4*)(ah + (size_t)r0 * lda);
        stg[1] = *(const uint4*)(ah + (size_t)(r0 + 64) * lda);
        stg[2] = *(const uint4*)(al + (size_t)r0 * lda);
        stg[3] = *(const uint4*)(al + (size_t)(r0 + 64) * lda);
        stg[4] = *(const uint4*)(bh + (size_t)r0 * ldb);
        stg[5] = *(const uint4*)(bh + (size_t)(r0 + 64) * ldb);
        stg[6] = *(const uint4*)(bl + (size_t)r0 * ldb);
        stg[7] = *(const uint4*)(bl + (size_t)(r0 + 64) * ldb);
    };
    auto sts_chunk = [&](int buf) {
        #pragma unroll
        for (int t = 0; t < 4; t++) {
            __nv_bfloat16* base = sm + (buf * 4 + t) * TILE_ELEMS;
            *(uint4*)(base + r0 * PITCH + seg * 8)         = stg[t * 2];
            *(uint4*)(base + (r0 + 64) * PITCH + seg * 8)  = stg[t * 2 + 1];
        }
    };

    uint32_t sm0 = smem_u32(sm);
    auto compute = [&](int buf) {
        uint32_t aAh = sm0 + (buf * 4 + 0) * TILE_ELEMS * 2;
        uint32_t aAl = sm0 + (buf * 4 + 1) * TILE_ELEMS * 2;
        uint32_t aBh = sm0 + (buf * 4 + 2) * TILE_ELEMS * 2;
        uint32_t aBl = sm0 + (buf * 4 + 3) * TILE_ELEMS * 2;
        #pragma unroll
        for (int h = 0; h < 2; h++) {
            uint32_t ah[4][4], al[4][4], bh[2][4], bl[2][4];
            uint32_t a_off = (uint32_t)((wm * 64 + (lane & 15)) * (PITCH * 2)
                                        + h * 32 + (lane >> 4) * 16);
            #pragma unroll
            for (int mt = 0; mt < 4; mt++) {
                ldm_x4(ah[mt], aAh + a_off + mt * 16 * (PITCH * 2));
                ldm_x4(al[mt], aAl + a_off + mt * 16 * (PITCH * 2));
            }
            int q = lane >> 3;
            uint32_t b_off = (uint32_t)((wn * 32 + (q >> 1) * 8 + (lane & 7)) * (PITCH * 2)
                                        + h * 32 + (q & 1) * 16);
            ldm_x4(bh[0], aBh + b_off);
            ldm_x4(bh[1], aBh + b_off + 16 * (PITCH * 2));
            ldm_x4(bl[0], aBl + b_off);
            ldm_x4(bl[1], aBl + b_off + 16 * (PITCH * 2));
            #pragma unroll
            for (int mt = 0; mt < 4; mt++) {
                #pragma unroll
                for (int nt = 0; nt < 4; nt++) {
                    const uint32_t* pbh = &bh[nt >> 1][(nt & 1) * 2];
                    const uint32_t* pbl = &bl[nt >> 1][(nt & 1) * 2];
                    mma_bf16(d[mt][nt], ah[mt], pbh);
                    mma_bf16(d[mt][nt], ah[mt], pbl);
                    mma_bf16(d[mt][nt], al[mt], pbh);
                }
            }
        }
    };

    ldg_chunk(0);
    sts_chunk(0);
    __syncthreads();
    for (int c = 0; c < nc; c++) {
        if (c + 1 < nc) ldg_chunk(c + 1);
        compute(c & 1);
        if (c + 1 < nc) sts_chunk((c + 1) & 1);
        __syncthreads();
    }

    if (stage == 0) {
        #pragma unroll
        for (int mt = 0; mt < 4; mt++) {
            int m = m0 + wm * 64 + mt * 16 + gid;
            #pragma unroll
            for (int nt = 0; nt < 4; nt++) {
                int cc = wn * 32 + nt * 8 + tg * 2;
                int gcol = by * 128 + cc;
                float bx = bias[cc], byv = bias[cc + 1];
                float v00 = d[mt][nt][0] + bx, v01 = d[mt][nt][1] + byv;
                float v10 = d[mt][nt][2] + bx, v11 = d[mt][nt][3] + byv;
                __nv_bfloat16 h0, l0, h1, l1;
                split_bf16(v00, h0, l0); split_bf16(v01, h1, l1);
                __nv_bfloat162 hp0 = {h0, h1}, lp0 = {l0, l1};
                split_bf16(v10, h0, l0); split_bf16(v11, h1, l1);
                __nv_bfloat162 hp1 = {h0, h1}, lp1 = {l0, l1};
                *(__nv_bfloat162*)&g_fh[(size_t)m * 256 + gcol] = hp0;
                *(__nv_bfloat162*)&g_fl[(size_t)m * 256 + gcol] = lp0;
                *(__nv_bfloat162*)&g_fh[(size_t)(m + 8) * 256 + gcol] = hp1;
                *(__nv_bfloat162*)&g_fl[(size_t)(m + 8) * 256 + gcol] = lp1;
            }
        }
    } else if (stage == 1) {
        // q|off fp32 -> g_qoff; k|v bf16 -> g_kvb
        #pragma unroll
        for (int mt = 0; mt < 4; mt++) {
            int m = m0 + wm * 64 + mt * 16 + gid;
            #pragma unroll
            for (int nt = 0; nt < 4; nt++) {
                int gc = by * 128 + wn * 32 + nt * 8 + tg * 2;
                if (gc >= 224) continue;
                float bx = g_bg[gc], byv = g_bg[gc + 1];
                float2 lo = make_float2(d[mt][nt][0] + bx, d[mt][nt][1] + byv);
                float2 hi = make_float2(d[mt][nt][2] + bx, d[mt][nt][3] + byv);
                if (gc < 80) {
                    *(float2*)(g_qoff + (size_t)m * 80 + gc) = lo;
                    *(float2*)(g_qoff + (size_t)(m + 8) * 80 + gc) = hi;
                } else {
                    __nv_bfloat162 blo = __float22bfloat162_rn(lo);
                    __nv_bfloat162 bhi = __float22bfloat162_rn(hi);
                    *(__nv_bfloat162*)(g_kvb + (size_t)m * 144 + gc - 80) = blo;
                    *(__nv_bfloat162*)(g_kvb + (size_t)(m + 8) * 144 + gc - 80) = bhi;
                }
            }
        }
    } else {
        int bidx = m0 >> 12;
        int pixbase = (m0 & 4095) + wm * 64;
        #pragma unroll
        for (int nt = 0; nt < 4; nt++) {
            int oc = by * 128 + wn * 32 + nt * 8 + tg * 2;
            float inv0 = rsqrtf(rvar[oc] + 1e-5f);
            float sc0 = gamma[oc] * inv0;
            float sh0 = beta[oc] - rmean[oc] * sc0;
            float inv1 = rsqrtf(rvar[oc + 1] + 1e-5f);
            float sc1 = gamma[oc + 1] * inv1;
            float sh1 = beta[oc + 1] - rmean[oc + 1] * sc1;
            float* o0 = out + ((size_t)(bidx * 256 + oc)) * NPIX;
            float* o1 = out + ((size_t)(bidx * 256 + oc + 1)) * NPIX;
            #pragma unroll
            for (int mt = 0; mt < 4; mt++) {
                int pix = pixbase + mt * 16 + gid;
                o0[pix]     = fmaxf(d[mt][nt][0] * sc0 + sh0, 0.f);
                o1[pix]     = fmaxf(d[mt][nt][1] * sc1 + sh1, 0.f);
                o0[pix + 8] = fmaxf(d[mt][nt][2] * sc0 + sh0, 0.f);
                o1[pix + 8] = fmaxf(d[mt][nt][3] * sc1 + sh1, 0.f);
            }
        }
    }
}

// ---------------- deformable point attention (2 warps / query, bf16 kv) --
__global__ void __launch_bounds__(512, 3) attention_kernel()
{
    __shared__ int    sIdx[8][128];
    __shared__ float  sW  [8][128];
    __shared__ float  sLogit[8][32];
    __shared__ float  sAttn[8][32];
    __shared__ float4 sPart[8][32];
    int tid = threadIdx.x;
    int warp = tid >> 5, lane = tid & 31;
    int q = warp & 7, half = warp >> 3;
    int m = blockIdx.x * 8 + q;
    int b = m >> 12;
    int n = m & (NPIX - 1);

    const float* row = g_qoff + (size_t)m * 80;

    // per-lane (point = lane) offsets -> 4 taps
    float2 d = *(const float2*)(row + 16 + 2 * lane);
    float sx = (float)(n & 63) + d.x;
    float sy = (float)(n >> 6) + d.y;
    float x0f = floorf(sx), y0f = floorf(sy);
    float wx = sx - x0f,    wy = sy - y0f;
    int ix0 = min(max((int)x0f, 0), WL - 1);
    int ix1 = min(max((int)x0f + 1, 0), WL - 1);
    int iy0 = min(max((int)y0f, 0), HL - 1);
    int iy1 = min(max((int)y0f + 1, 0), HL - 1);
    // tap indices in BYTES (row = 144 bf16 = 288 B)
    int g00 = (iy0 * WL + ix0) * 288, g01 = (iy0 * WL + ix1) * 288;
    int g10 = (iy1 * WL + ix0) * 288, g11 = (iy1 * WL + ix1) * 288;
    float w00 = (1.f - wx) * (1.f - wy), w01 = wx * (1.f - wy);
    float w10 = (1.f - wx) * wy,         w11 = wx * wy;

    int cq = lane & 3;
    int oct = lane >> 2;
    float4 qv = *(const float4*)(row + 4 * cq);
    const char* kvB = (const char*)(g_kvb + (size_t)b * NPIX * 144);

    // phase 1: this warp handles point groups {half*2, half*2+1}
    #pragma unroll
    for (int gi = 0; gi < 2; gi++) {
        int g = half * 2 + gi;
        int src = oct + 8 * g;
        int G0 = __shfl_sync(0xffffffffu, g00, src);
        int G1 = __shfl_sync(0xffffffffu, g01, src);
        int G2 = __shfl_sync(0xffffffffu, g10, src);
        int G3 = __shfl_sync(0xffffffffu, g11, src);
        float W0 = __shfl_sync(0xffffffffu, w00, src);
        float W1 = __shfl_sync(0xffffffffu, w01, src);
        float W2 = __shfl_sync(0xffffffffu, w10, src);
        float W3 = __shfl_sync(0xffffffffu, w11, src);
        uint2 kp0 = *(const uint2*)(kvB + G0 + cq * 8);
        uint2 kp1 = *(const uint2*)(kvB + G1 + cq * 8);
        uint2 kp2 = *(const uint2*)(kvB + G2 + cq * 8);
        uint2 kp3 = *(const uint2*)(kvB + G3 + cq * 8);
        float ksx = W0 * bfu_lo(kp0.x) + W1 * bfu_lo(kp1.x) + W2 * bfu_lo(kp2.x) + W3 * bfu_lo(kp3.x);
        float ksy = W0 * bfu_hi(kp0.x) + W1 * bfu_hi(kp1.x) + W2 * bfu_hi(kp2.x) + W3 * bfu_hi(kp3.x);
        float ksz = W0 * bfu_lo(kp0.y) + W1 * bfu_lo(kp1.y) + W2 * bfu_lo(kp2.y) + W3 * bfu_lo(kp3.y);
        float ksw = W0 * bfu_hi(kp0.y) + W1 * bfu_hi(kp1.y) + W2 * bfu_hi(kp2.y) + W3 * bfu_hi(kp3.y);
        float part = qv.x * ksx + qv.y * ksy + qv.z * ksz + qv.w * ksw;
        part += __shfl_xor_sync(0xffffffffu, part, 1);
        part += __shfl_xor_sync(0xffffffffu, part, 2);
        if (cq == 0) sLogit[q][src] = part * 0.25f;   // 1/sqrt(16)
        int   Gq = (cq == 0) ? G0 : (cq == 1) ? G1 : (cq == 2) ? G2 : G3;
        float Wq = (cq == 0) ? W0 : (cq == 1) ? W1 : (cq == 2) ? W2 : W3;
        sIdx[q][src * 4 + cq] = Gq;
        sW  [q][src * 4 + cq] = Wq;
    }
    __syncthreads();

    // softmax over 32 points (both pair warps compute identically)
    float lg = sLogit[q][lane];
    float mx = lg;
    #pragma unroll
    for (int s = 16; s; s >>= 1) mx = fmaxf(mx, __shfl_xor_sync(0xffffffffu, mx, s));
    float e = __expf(lg - mx);
    float sum = e;
    #pragma unroll
    for (int s = 16; s; s >>= 1) sum += __shfl_xor_sync(0xffffffffu, sum, s);
    sAttn[q][lane] = e / sum;
    __syncwarp();

    // phase 2: this warp gathers taps [half*64, half*64+64); 4 bf16 ch/lane
    float4 acc = make_float4(0.f, 0.f, 0.f, 0.f);
    int base = half * 64;
    int loff = 32 + lane * 8;   // v starts at byte 32 of the row
    #pragma unroll 4
    for (int t = 0; t < 64; t += 4) {
        int tt = base + t;
        int4   i4 = *(const int4*)&sIdx[q][tt];
        float4 w4 = *(const float4*)&sW[q][tt];
        float a = sAttn[q][tt >> 2];
        w4.x *= a; w4.y *= a; w4.z *= a; w4.w *= a;
        uint2 p0 = *(const uint2*)(kvB + i4.x + loff);
        uint2 p1 = *(const uint2*)(kvB + i4.y + loff);
        uint2 p2 = *(const uint2*)(kvB + i4.z + loff);
        uint2 p3 = *(const uint2*)(kvB + i4.w + loff);
        acc.x += w4.x * bfu_lo(p0.x) + w4.y * bfu_lo(p1.x) + w4.z * bfu_lo(p2.x) + w4.w * bfu_lo(p3.x);
        acc.y += w4.x * bfu_hi(p0.x) + w4.y * bfu_hi(p1.x) + w4.z * bfu_hi(p2.x) + w4.w * bfu_hi(p3.x);
        acc.z += w4.x * bfu_lo(p0.y) + w4.y * bfu_lo(p1.y) + w4.z * bfu_lo(p2.y) + w4.w * bfu_lo(p3.y);
        acc.w += w4.x * bfu_hi(p0.y) + w4.y * bfu_hi(p1.y) + w4.z * bfu_hi(p2.y) + w4.w * bfu_hi(p3.y);
    }
    if (half) sPart[q][lane] = acc;
    __syncthreads();
    if (!half) {
        float4 p = sPart[q][lane];
        acc.x += p.x; acc.y += p.y; acc.z += p.z; acc.w += p.w;
        size_t obase = (size_t)m * 128 + lane * 4;
        __nv_bfloat16 hv[4], lv[4];
        split_bf16(acc.x, hv[0], lv[0]);
        split_bf16(acc.y, hv[1], lv[1]);
        split_bf16(acc.z, hv[2], lv[2]);
        split_bf16(acc.w, hv[3], lv[3]);
        *(uint2*)&g_attn_h[obase] = *(uint2*)hv;
        *(uint2*)&g_attn_l[obase] = *(uint2*)lv;
    }
}

// ---------------- launch ------------------------------------------------
extern "C" void kernel_launch(void* const* d_in, const int* in_sizes, int n_in,
                              void* d_out, int out_size) {
    const float* low   = (const float*)d_in[0];
    const float* high  = (const float*)d_in[1];
    const float* W1    = (const float*)d_in[2];
    const float* b1    = (const float*)d_in[3];
    const float* W2    = (const float*)d_in[4];
    const float* b2    = (const float*)d_in[5];
    const float* Wq    = (const float*)d_in[6];
    const float* bq    = (const float*)d_in[7];
    const float* Wk    = (const float*)d_in[8];
    const float* bk    = (const float*)d_in[9];
    const float* Wv    = (const float*)d_in[10];
    const float* bv    = (const float*)d_in[11];
    const float* Woff  = (const float*)d_in[12];
    const float* boff  = (const float*)d_in[13];
    const float* Wb    = (const float*)d_in[14];
    const float* gamma = (const float*)d_in[15];
    const float* beta  = (const float*)d_in[16];
    const float* rmean = (const float*)d_in[17];
    const float* rvar  = (const float*)d_in[18];
    float* out = (float*)d_out;

    const int HMMA_SMEM = 2 * 4 * TILE_ELEMS * 2;  // 81920 bytes
    cudaFuncSetAttribute(hmma_kernel, cudaFuncAttributeMaxDynamicSharedMemorySize, HMMA_SMEM);

    prep_kernel<<<4160, 256>>>(high, low, W1, W2, Wb,
                               Wq, bq, Woff, boff, Wk, bk, Wv, bv);
    hmma_kernel<<<dim3(64, 2), 256, HMMA_SMEM>>>(
        0, b1, b2, nullptr, nullptr, nullptr, nullptr, nullptr);
    hmma_kernel<<<dim3(64, 2), 256, HMMA_SMEM>>>(
        1, nullptr, nullptr, nullptr, nullptr, nullptr, nullptr, nullptr);
    attention_kernel<<<MTOT / 8, 512>>>();
    hmma_kernel<<<dim3(64, 2), 256, HMMA_SMEM>>>(
        2, nullptr, nullptr, gamma, beta, rmean, rvar, out);
}

// round 9
// speedup vs baseline: 2.6654x; 1.0459x over previous
#include <cuda_runtime.h>
#include <cuda_bf16.h>
#include <math.h>
#include <stdint.h>

// ---------------- problem constants ----------------
#define NB   2
#define CH   256
#define INC  128
#define ITC  16
#define NPT  32
#define HL   64
#define WL   64
#define NPIX 4096
#define HH   32
#define WH   32
#define MTOT (NB * NPIX)   // 8192 rows (batch folded into M)

// ---------------- scratch (__device__ globals, no allocs) ----------------
__device__ __align__(16) __nv_bfloat16 g_c1h[MTOT * 512];  // cat1 hi
__device__ __align__(16) __nv_bfloat16 g_c1l[MTOT * 512];  // cat1 lo
__device__ __align__(16) __nv_bfloat16 g_fh [MTOT * 256];  // qf|vf hi
__device__ __align__(16) __nv_bfloat16 g_fl [MTOT * 256];  // qf|vf lo
__device__ __align__(16) float g_qoff[MTOT * 80];          // q[16] | off[64] fp32
__device__ __align__(16) __nv_bfloat16 g_kvb[MTOT * 144];  // k[16] | v[128] bf16 (288B rows)
__device__ __align__(16) __nv_bfloat16 g_attn_h[MTOT * 128];
__device__ __align__(16) __nv_bfloat16 g_attn_l[MTOT * 128];
__device__ __align__(16) __nv_bfloat16 g_W1h[128 * 512], g_W1l[128 * 512];
__device__ __align__(16) __nv_bfloat16 g_W2h[128 * 256], g_W2l[128 * 256];
__device__ __align__(16) __nv_bfloat16 g_Wbh[256 * 384], g_Wbl[256 * 384];
__device__ __align__(16) __nv_bfloat16 g_Wgh[256 * 256], g_Wgl[256 * 256];  // block-diag [q;off;k;v]
__device__ float g_bg[256];

// ---------------- mma.sync helpers ----------------
__device__ __forceinline__ uint32_t smem_u32(const void* p) {
    uint32_t a;
    asm("{ .reg .u64 t; cvta.to.shared.u64 t, %1; cvt.u32.u64 %0, t; }" : "=r"(a) : "l"(p));
    return a;
}
__device__ __forceinline__ void ldm_x4(uint32_t* r, uint32_t addr) {
    asm volatile("ldmatrix.sync.aligned.m8n8.x4.shared.b16 {%0,%1,%2,%3}, [%4];"
        : "=r"(r[0]), "=r"(r[1]), "=r"(r[2]), "=r"(r[3]) : "r"(addr));
}
__device__ __forceinline__ void mma_bf16(float* d, const uint32_t* a, const uint32_t* b) {
    asm volatile("mma.sync.aligned.m16n8k16.row.col.f32.bf16.bf16.f32 "
        "{%0,%1,%2,%3}, {%4,%5,%6,%7}, {%8,%9}, {%0,%1,%2,%3};"
        : "+f"(d[0]), "+f"(d[1]), "+f"(d[2]), "+f"(d[3])
        : "r"(a[0]), "r"(a[1]), "r"(a[2]), "r"(a[3]), "r"(b[0]), "r"(b[1]));
}

__device__ __forceinline__ void split_bf16(float x, __nv_bfloat16& h, __nv_bfloat16& l) {
    h = __float2bfloat16(x);
    l = __float2bfloat16(x - __bfloat162float(h));
}
// bf16x2 word -> two fp32 via pure bit ops (exact; no CVT pipe)
__device__ __forceinline__ float bfu_lo(uint32_t u) { return __uint_as_float(u << 16); }
__device__ __forceinline__ float bfu_hi(uint32_t u) { return __uint_as_float(u & 0xffff0000u); }
// packed bf16x2 fma: d += a*b (HFMA2.BF16_V2, fma pipe)
__device__ __forceinline__ void hfma2b(uint32_t& d, uint32_t a, uint32_t b) {
    asm("fma.rn.bf16x2 %0, %1, %2, %0;" : "+r"(d) : "r"(a), "r"(b));
}
// duplicate fp32 into both lanes of a bf16x2 word
__device__ __forceinline__ uint32_t bf16x2_dup(float x) {
    uint32_t r;
    asm("cvt.rn.bf16x2.f32 %0, %1, %1;" : "=r"(r) : "f"(x));
    return r;
}

// ---------------- prep: upsample + transpose -> bf16 splits; weight packing --
__global__ void __launch_bounds__(256) prep_kernel(
    const float* __restrict__ high, const float* __restrict__ low,
    const float* __restrict__ W1, const float* __restrict__ W2,
    const float* __restrict__ Wb,
    const float* __restrict__ Wq, const float* __restrict__ bq,
    const float* __restrict__ Woff, const float* __restrict__ boff,
    const float* __restrict__ Wk, const float* __restrict__ bk,
    const float* __restrict__ Wv, const float* __restrict__ bv)
{
    int blk = blockIdx.x;
    int tid = threadIdx.x;

    if (blk >= 4096) {
        for (int e = (blk - 4096) * 256 + tid; e < 262400; e += 16384) {
            if (e < 65536) {
                split_bf16(W1[e], g_W1h[e], g_W1l[e]);
            } else if (e < 98304) {
                int t = e - 65536;
                split_bf16(W2[t], g_W2h[t], g_W2l[t]);
            } else if (e < 196608) {
                int t = e - 98304;
                split_bf16(Wb[t], g_Wbh[t], g_Wbl[t]);
            } else if (e < 262144) {
                int t = e - 196608;
                int r = t >> 8, k = t & 255;
                float v = 0.f;
                if (r < 16)       { if (k < 128)  v = Wq[r * 128 + k]; }
                else if (r < 80)  { if (k < 128)  v = Woff[(r - 16) * 128 + k]; }
                else if (r < 96)  { if (k >= 128) v = Wk[(r - 80) * 128 + k - 128]; }
                else if (r < 224) { if (k >= 128) v = Wv[(r - 96) * 128 + k - 128]; }
                split_bf16(v, g_Wgh[t], g_Wgl[t]);
            } else {
                int i = e - 262144;
                float v = 0.f;
                if (i < 16)       v = bq[i];
                else if (i < 80)  v = boff[i - 16];
                else if (i < 96)  v = bk[i - 80];
                else if (i < 224) v = bv[i - 96];
                g_bg[i] = v;
            }
        }
        return;
    }

    int part = blk >> 11;          // 0: high_up, 1: low
    int r = blk & 2047;
    int b = r >> 10;
    int r2 = r & 1023;
    int pt = r2 >> 3;
    int ct = r2 & 7;
    int p0 = pt * 32;
    int c0 = ct * 32;

    __shared__ float s[32][33];
    int px = tid & 31;
    int cq = tid >> 5;

    if (part == 1) {
        #pragma unroll
        for (int i = 0; i < 4; i++) {
            int c = cq * 4 + i;
            s[c][px] = low[((size_t)(b * CH + c0 + c)) * NPIX + p0 + px];
        }
    } else {
        int y = p0 >> 6;
        int xb = p0 & 63;
        float fy = y * 0.5f - 0.25f;
        float y0f = floorf(fy);
        float wy = fy - y0f;
        int iy0 = min(max((int)y0f, 0), HH - 1);
        int iy1 = min(max((int)y0f + 1, 0), HH - 1);
        int x = xb + px;
        float fx = x * 0.5f - 0.25f;
        float x0f = floorf(fx);
        float wx = fx - x0f;
        int ix0 = min(max((int)x0f, 0), WH - 1);
        int ix1 = min(max((int)x0f + 1, 0), WH - 1);
        #pragma unroll
        for (int i = 0; i < 4; i++) {
            int c = cq * 4 + i;
            const float* src = high + ((size_t)(b * CH + c0 + c)) * (HH * WH);
            float v00 = src[iy0 * WH + ix0], v01 = src[iy0 * WH + ix1];
            float v10 = src[iy1 * WH + ix0], v11 = src[iy1 * WH + ix1];
            s[c][px] = (1.f - wx) * (1.f - wy) * v00 + wx * (1.f - wy) * v01
                     + (1.f - wx) * wy * v10 + wx * wy * v11;
        }
    }
    __syncthreads();

    int cc = tid & 31;
    int pq = tid >> 5;
    int base_c = (part == 0 ? c0 : 256 + c0) + cc;
    #pragma unroll
    for (int i = 0; i < 4; i++) {
        int pp = pq * 4 + i;
        size_t idx = ((size_t)(b * NPIX + p0 + pp)) * 512 + base_c;
        __nv_bfloat16 h, l;
        split_bf16(s[cc][pp], h, l);
        g_c1h[idx] = h;
        g_c1l[idx] = l;
    }
}

// ---------------- bf16x3 mma.sync GEMM (stages 0,1,2) --------------------
#define PITCH 40
#define TILE_ELEMS (128 * PITCH)

__global__ void __launch_bounds__(256) hmma_kernel(
    int stage,
    const float* __restrict__ bias0, const float* __restrict__ bias1,
    const float* __restrict__ gamma, const float* __restrict__ beta,
    const float* __restrict__ rmean, const float* __restrict__ rvar,
    float* __restrict__ out)
{
    extern __shared__ __nv_bfloat16 sm[];
    int tid = threadIdx.x;
    int wid = tid >> 5, lane = tid & 31;
    int wm = wid >> 2, wn = wid & 3;
    int gid = lane >> 2, tg = lane & 3;
    int m0 = blockIdx.x * 128;
    int by = blockIdx.y;

    int K, ldb;
    const __nv_bfloat16 *Bh, *Bl;
    const float* bias = nullptr;
    if (stage == 0) {
        if (by == 0) { K = 512; Bh = g_W1h; Bl = g_W1l; ldb = 512; bias = bias0; }
        else         { K = 256; Bh = g_W2h; Bl = g_W2l; ldb = 256; bias = bias1; }
    } else if (stage == 1) {
        K = 256; ldb = 256;
        Bh = g_Wgh + (size_t)by * 128 * 256;
        Bl = g_Wgl + (size_t)by * 128 * 256;
    } else {
        K = 384; ldb = 384;
        Bh = g_Wbh + (size_t)by * 128 * 384;
        Bl = g_Wbl + (size_t)by * 128 * 384;
    }
    int nc = K >> 5;

    float d[4][4][4];
    #pragma unroll
    for (int i = 0; i < 4; i++)
        #pragma unroll
        for (int j = 0; j < 4; j++)
            #pragma unroll
            for (int k = 0; k < 4; k++) d[i][j][k] = 0.f;

    int seg = tid & 3;
    int r0 = tid >> 2;

    uint4 stg[8];
    auto ldg_chunk = [&](int c) {
        const __nv_bfloat16 *Ah_src, *Al_src;
        int lda, colA;
        if (stage == 0)      { Ah_src = g_c1h; Al_src = g_c1l; lda = 512; colA = c * 32; }
        else if (stage == 1) { Ah_src = g_fh;  Al_src = g_fl;  lda = 256; colA = c * 32; }
        else if (c < 4)      { Ah_src = g_attn_h; Al_src = g_attn_l; lda = 128; colA = c * 32; }
        else                 { Ah_src = g_c1h; Al_src = g_c1l; lda = 512; colA = (c - 4) * 32; }
        const __nv_bfloat16* ah = Ah_src + (size_t)m0 * lda + colA + seg * 8;
        const __nv_bfloat16* al = Al_src + (size_t)m0 * lda + colA + seg * 8;
        const __nv_bfloat16* bh = Bh + c * 32 + seg * 8;
        const __nv_bfloat16* bl = Bl + c * 32 + seg * 8;
        stg[0] = *(const uint4*)(ah + (size_t)r0 * lda);
        stg[1] = *(const uint4*)(ah + (size_t)(r0 + 64) * lda);
        stg[2] = *(const uint4*)(al + (size_t)r0 * lda);
        stg[3] = *(const uint4*)(al + (size_t)(r0 + 64) * lda);
        stg[4] = *(const uint4*)(bh + (size_t)r0 * ldb);
        stg[5] = *(const uint4*)(bh + (size_t)(r0 + 64) * ldb);
        stg[6] = *(const uint4*)(bl + (size_t)r0 * ldb);
        stg[7] = *(const uint4*)(bl + (size_t)(r0 + 64) * ldb);
    };
    auto sts_chunk = [&](int buf) {
        #pragma unroll
        for (int t = 0; t < 4; t++) {
            __nv_bfloat16* base = sm + (buf * 4 + t) * TILE_ELEMS;
            *(uint4*)(base + r0 * PITCH + seg * 8)         = stg[t * 2];
            *(uint4*)(base + (r0 + 64) * PITCH + seg * 8)  = stg[t * 2 + 1];
        }
    };

    uint32_t sm0 = smem_u32(sm);
    auto compute = [&](int buf) {
        uint32_t aAh = sm0 + (buf * 4 + 0) * TILE_ELEMS * 2;
        uint32_t aAl = sm0 + (buf * 4 + 1) * TILE_ELEMS * 2;
        uint32_t aBh = sm0 + (buf * 4 + 2) * TILE_ELEMS * 2;
        uint32_t aBl = sm0 + (buf * 4 + 3) * TILE_ELEMS * 2;
        #pragma unroll
        for (int h = 0; h < 2; h++) {
            uint32_t ah[4][4], al[4][4], bh[2][4], bl[2][4];
            uint32_t a_off = (uint32_t)((wm * 64 + (lane & 15)) * (PITCH * 2)
                                        + h * 32 + (lane >> 4) * 16);
            #pragma unroll
            for (int mt = 0; mt < 4; mt++) {
                ldm_x4(ah[mt], aAh + a_off + mt * 16 * (PITCH * 2));
                ldm_x4(al[mt], aAl + a_off + mt * 16 * (PITCH * 2));
            }
            int q = lane >> 3;
            uint32_t b_off = (uint32_t)((wn * 32 + (q >> 1) * 8 + (lane & 7)) * (PITCH * 2)
                                        + h * 32 + (q & 1) * 16);
            ldm_x4(bh[0], aBh + b_off);
            ldm_x4(bh[1], aBh + b_off + 16 * (PITCH * 2));
            ldm_x4(bl[0], aBl + b_off);
            ldm_x4(bl[1], aBl + b_off + 16 * (PITCH * 2));
            #pragma unroll
            for (int mt = 0; mt < 4; mt++) {
                #pragma unroll
                for (int nt = 0; nt < 4; nt++) {
                    const uint32_t* pbh = &bh[nt >> 1][(nt & 1) * 2];
                    const uint32_t* pbl = &bl[nt >> 1][(nt & 1) * 2];
                    mma_bf16(d[mt][nt], ah[mt], pbh);
                    mma_bf16(d[mt][nt], ah[mt], pbl);
                    mma_bf16(d[mt][nt], al[mt], pbh);
                }
            }
        }
    };

    ldg_chunk(0);
    sts_chunk(0);
    __syncthreads();
    for (int c = 0; c < nc; c++) {
        if (c + 1 < nc) ldg_chunk(c + 1);
        compute(c & 1);
        if (c + 1 < nc) sts_chunk((c + 1) & 1);
        __syncthreads();
    }

    if (stage == 0) {
        #pragma unroll
        for (int mt = 0; mt < 4; mt++) {
            int m = m0 + wm * 64 + mt * 16 + gid;
            #pragma unroll
            for (int nt = 0; nt < 4; nt++) {
                int cc = wn * 32 + nt * 8 + tg * 2;
                int gcol = by * 128 + cc;
                float bx = bias[cc], byv = bias[cc + 1];
                float v00 = d[mt][nt][0] + bx, v01 = d[mt][nt][1] + byv;
                float v10 = d[mt][nt][2] + bx, v11 = d[mt][nt][3] + byv;
                __nv_bfloat16 h0, l0, h1, l1;
                split_bf16(v00, h0, l0); split_bf16(v01, h1, l1);
                __nv_bfloat162 hp0 = {h0, h1}, lp0 = {l0, l1};
                split_bf16(v10, h0, l0); split_bf16(v11, h1, l1);
                __nv_bfloat162 hp1 = {h0, h1}, lp1 = {l0, l1};
                *(__nv_bfloat162*)&g_fh[(size_t)m * 256 + gcol] = hp0;
                *(__nv_bfloat162*)&g_fl[(size_t)m * 256 + gcol] = lp0;
                *(__nv_bfloat162*)&g_fh[(size_t)(m + 8) * 256 + gcol] = hp1;
                *(__nv_bfloat162*)&g_fl[(size_t)(m + 8) * 256 + gcol] = lp1;
            }
        }
    } else if (stage == 1) {
        // q|off fp32 -> g_qoff; k|v bf16 -> g_kvb
        #pragma unroll
        for (int mt = 0; mt < 4; mt++) {
            int m = m0 + wm * 64 + mt * 16 + gid;
            #pragma unroll
            for (int nt = 0; nt < 4; nt++) {
                int gc = by * 128 + wn * 32 + nt * 8 + tg * 2;
                if (gc >= 224) continue;
                float bx = g_bg[gc], byv = g_bg[gc + 1];
                float2 lo = make_float2(d[mt][nt][0] + bx, d[mt][nt][1] + byv);
                float2 hi = make_float2(d[mt][nt][2] + bx, d[mt][nt][3] + byv);
                if (gc < 80) {
                    *(float2*)(g_qoff + (size_t)m * 80 + gc) = lo;
                    *(float2*)(g_qoff + (size_t)(m + 8) * 80 + gc) = hi;
                } else {
                    __nv_bfloat162 blo = __float22bfloat162_rn(lo);
                    __nv_bfloat162 bhi = __float22bfloat162_rn(hi);
                    *(__nv_bfloat162*)(g_kvb + (size_t)m * 144 + gc - 80) = blo;
                    *(__nv_bfloat162*)(g_kvb + (size_t)(m + 8) * 144 + gc - 80) = bhi;
                }
            }
        }
    } else {
        int bidx = m0 >> 12;
        int pixbase = (m0 & 4095) + wm * 64;
        #pragma unroll
        for (int nt = 0; nt < 4; nt++) {
            int oc = by * 128 + wn * 32 + nt * 8 + tg * 2;
            float inv0 = rsqrtf(rvar[oc] + 1e-5f);
            float sc0 = gamma[oc] * inv0;
            float sh0 = beta[oc] - rmean[oc] * sc0;
            float inv1 = rsqrtf(rvar[oc + 1] + 1e-5f);
            float sc1 = gamma[oc + 1] * inv1;
            float sh1 = beta[oc + 1] - rmean[oc + 1] * sc1;
            float* o0 = out + ((size_t)(bidx * 256 + oc)) * NPIX;
            float* o1 = out + ((size_t)(bidx * 256 + oc + 1)) * NPIX;
            #pragma unroll
            for (int mt = 0; mt < 4; mt++) {
                int pix = pixbase + mt * 16 + gid;
                o0[pix]     = fmaxf(d[mt][nt][0] * sc0 + sh0, 0.f);
                o1[pix]     = fmaxf(d[mt][nt][1] * sc1 + sh1, 0.f);
                o0[pix + 8] = fmaxf(d[mt][nt][2] * sc0 + sh0, 0.f);
                o1[pix + 8] = fmaxf(d[mt][nt][3] * sc1 + sh1, 0.f);
            }
        }
    }
}

// ---------------- deformable point attention (2 warps / query, bf16 kv,
//                   packed-HFMA2 phase 2) --------------------------------
__global__ void __launch_bounds__(512, 3) attention_kernel()
{
    __shared__ int    sIdx[8][128];
    __shared__ float  sW  [8][128];     // phase1: float weight; after fold: bf16x2-dup (uint)
    __shared__ float  sLogit[8][32];
    __shared__ float  sAttn[8][32];
    __shared__ float4 sPart[8][32];
    int tid = threadIdx.x;
    int warp = tid >> 5, lane = tid & 31;
    int q = warp & 7, half = warp >> 3;
    int m = blockIdx.x * 8 + q;
    int b = m >> 12;
    int n = m & (NPIX - 1);

    const float* row = g_qoff + (size_t)m * 80;

    // per-lane (point = lane) offsets -> 4 taps
    float2 d = *(const float2*)(row + 16 + 2 * lane);
    float sx = (float)(n & 63) + d.x;
    float sy = (float)(n >> 6) + d.y;
    float x0f = floorf(sx), y0f = floorf(sy);
    float wx = sx - x0f,    wy = sy - y0f;
    int ix0 = min(max((int)x0f, 0), WL - 1);
    int ix1 = min(max((int)x0f + 1, 0), WL - 1);
    int iy0 = min(max((int)y0f, 0), HL - 1);
    int iy1 = min(max((int)y0f + 1, 0), HL - 1);
    // tap indices in BYTES (row = 144 bf16 = 288 B)
    int g00 = (iy0 * WL + ix0) * 288, g01 = (iy0 * WL + ix1) * 288;
    int g10 = (iy1 * WL + ix0) * 288, g11 = (iy1 * WL + ix1) * 288;
    float w00 = (1.f - wx) * (1.f - wy), w01 = wx * (1.f - wy);
    float w10 = (1.f - wx) * wy,         w11 = wx * wy;

    int cq = lane & 3;
    int oct = lane >> 2;
    float4 qv = *(const float4*)(row + 4 * cq);
    const char* kvB = (const char*)(g_kvb + (size_t)b * NPIX * 144);

    // phase 1: this warp handles point groups {half*2, half*2+1}
    #pragma unroll
    for (int gi = 0; gi < 2; gi++) {
        int g = half * 2 + gi;
        int src = oct + 8 * g;
        int G0 = __shfl_sync(0xffffffffu, g00, src);
        int G1 = __shfl_sync(0xffffffffu, g01, src);
        int G2 = __shfl_sync(0xffffffffu, g10, src);
        int G3 = __shfl_sync(0xffffffffu, g11, src);
        float W0 = __shfl_sync(0xffffffffu, w00, src);
        float W1 = __shfl_sync(0xffffffffu, w01, src);
        float W2 = __shfl_sync(0xffffffffu, w10, src);
        float W3 = __shfl_sync(0xffffffffu, w11, src);
        uint2 kp0 = *(const uint2*)(kvB + G0 + cq * 8);
        uint2 kp1 = *(const uint2*)(kvB + G1 + cq * 8);
        uint2 kp2 = *(const uint2*)(kvB + G2 + cq * 8);
        uint2 kp3 = *(const uint2*)(kvB + G3 + cq * 8);
        float ksx = W0 * bfu_lo(kp0.x) + W1 * bfu_lo(kp1.x) + W2 * bfu_lo(kp2.x) + W3 * bfu_lo(kp3.x);
        float ksy = W0 * bfu_hi(kp0.x) + W1 * bfu_hi(kp1.x) + W2 * bfu_hi(kp2.x) + W3 * bfu_hi(kp3.x);
        float ksz = W0 * bfu_lo(kp0.y) + W1 * bfu_lo(kp1.y) + W2 * bfu_lo(kp2.y) + W3 * bfu_lo(kp3.y);
        float ksw = W0 * bfu_hi(kp0.y) + W1 * bfu_hi(kp1.y) + W2 * bfu_hi(kp2.y) + W3 * bfu_hi(kp3.y);
        float part = qv.x * ksx + qv.y * ksy + qv.z * ksz + qv.w * ksw;
        part += __shfl_xor_sync(0xffffffffu, part, 1);
        part += __shfl_xor_sync(0xffffffffu, part, 2);
        if (cq == 0) sLogit[q][src] = part * 0.25f;   // 1/sqrt(16)
        int   Gq = (cq == 0) ? G0 : (cq == 1) ? G1 : (cq == 2) ? G2 : G3;
        float Wq = (cq == 0) ? W0 : (cq == 1) ? W1 : (cq == 2) ? W2 : W3;
        sIdx[q][src * 4 + cq] = Gq;
        sW  [q][src * 4 + cq] = Wq;
    }
    __syncthreads();

    // softmax over 32 points (both pair warps compute identically)
    float lg = sLogit[q][lane];
    float mx = lg;
    #pragma unroll
    for (int s = 16; s; s >>= 1) mx = fmaxf(mx, __shfl_xor_sync(0xffffffffu, mx, s));
    float e = __expf(lg - mx);
    float sum = e;
    #pragma unroll
    for (int s = 16; s; s >>= 1) sum += __shfl_xor_sync(0xffffffffu, sum, s);
    sAttn[q][lane] = e / sum;
    __syncwarp();

    // pre-fold attn into tap weights, pack as dup'd bf16x2 (own half only)
    int base = half * 64;
    uint32_t* sWp = (uint32_t*)&sW[q][0];
    #pragma unroll
    for (int j = 0; j < 2; j++) {
        int tt = base + j * 32 + lane;
        float w = sW[q][tt] * sAttn[q][tt >> 2];
        sWp[tt] = bf16x2_dup(w);
    }
    __syncwarp();

    // phase 2: packed bf16x2 gather-accumulate, flush every 4 taps
    float4 acc = make_float4(0.f, 0.f, 0.f, 0.f);
    int loff = 32 + lane * 8;   // v starts at byte 32 of the row
    #pragma unroll 4
    for (int t = 0; t < 64; t += 4) {
        int tt = base + t;
        int4  i4  = *(const int4*)&sIdx[q][tt];
        uint4 wp4 = *(const uint4*)&sWp[tt];
        uint2 p0 = *(const uint2*)(kvB + i4.x + loff);
        uint2 p1 = *(const uint2*)(kvB + i4.y + loff);
        uint2 p2 = *(const uint2*)(kvB + i4.z + loff);
        uint2 p3 = *(const uint2*)(kvB + i4.w + loff);
        uint32_t a0 = 0, a1 = 0;
        hfma2b(a0, wp4.x, p0.x);  hfma2b(a1, wp4.x, p0.y);
        hfma2b(a0, wp4.y, p1.x);  hfma2b(a1, wp4.y, p1.y);
        hfma2b(a0, wp4.z, p2.x);  hfma2b(a1, wp4.z, p2.y);
        hfma2b(a0, wp4.w, p3.x);  hfma2b(a1, wp4.w, p3.y);
        acc.x += bfu_lo(a0);  acc.y += bfu_hi(a0);
        acc.z += bfu_lo(a1);  acc.w += bfu_hi(a1);
    }
    if (half) sPart[q][lane] = acc;
    __syncthreads();
    if (!half) {
        float4 p = sPart[q][lane];
        acc.x += p.x; acc.y += p.y; acc.z += p.z; acc.w += p.w;
        size_t obase = (size_t)m * 128 + lane * 4;
        __nv_bfloat16 hv[4], lv[4];
        split_bf16(acc.x, hv[0], lv[0]);
        split_bf16(acc.y, hv[1], lv[1]);
        split_bf16(acc.z, hv[2], lv[2]);
        split_bf16(acc.w, hv[3], lv[3]);
        *(uint2*)&g_attn_h[obase] = *(uint2*)hv;
        *(uint2*)&g_attn_l[obase] = *(uint2*)lv;
    }
}

// ---------------- launch ------------------------------------------------
extern "C" void kernel_launch(void* const* d_in, const int* in_sizes, int n_in,
                              void* d_out, int out_size) {
    const float* low   = (const float*)d_in[0];
    const float* high  = (const float*)d_in[1];
    const float* W1    = (const float*)d_in[2];
    const float* b1    = (const float*)d_in[3];
    const float* W2    = (const float*)d_in[4];
    const float* b2    = (const float*)d_in[5];
    const float* Wq    = (const float*)d_in[6];
    const float* bq    = (const float*)d_in[7];
    const float* Wk    = (const float*)d_in[8];
    const float* bk    = (const float*)d_in[9];
    const float* Wv    = (const float*)d_in[10];
    const float* bv    = (const float*)d_in[11];
    const float* Woff  = (const float*)d_in[12];
    const float* boff  = (const float*)d_in[13];
    const float* Wb    = (const float*)d_in[14];
    const float* gamma = (const float*)d_in[15];
    const float* beta  = (const float*)d_in[16];
    const float* rmean = (const float*)d_in[17];
    const float* rvar  = (const float*)d_in[18];
    float* out = (float*)d_out;

    const int HMMA_SMEM = 2 * 4 * TILE_ELEMS * 2;  // 81920 bytes
    cudaFuncSetAttribute(hmma_kernel, cudaFuncAttributeMaxDynamicSharedMemorySize, HMMA_SMEM);

    prep_kernel<<<4160, 256>>>(high, low, W1, W2, Wb,
                               Wq, bq, Woff, boff, Wk, bk, Wv, bv);
    hmma_kernel<<<dim3(64, 2), 256, HMMA_SMEM>>>(
        0, b1, b2, nullptr, nullptr, nullptr, nullptr, nullptr);
    hmma_kernel<<<dim3(64, 2), 256, HMMA_SMEM>>>(
        1, nullptr, nullptr, nullptr, nullptr, nullptr, nullptr, nullptr);
    attention_kernel<<<MTOT / 8, 512>>>();
    hmma_kernel<<<dim3(64, 2), 256, HMMA_SMEM>>>(
        2, nullptr, nullptr, gamma, beta, rmean, rvar, out);
}